// round 1
// baseline (speedup 1.0000x reference)
#include <cuda_runtime.h>

#define NB 32
#define CC 512
#define AA 256
#define HH 64
#define WW 64
#define HWD 4096
#define PHW 1024

// Scratch (static device globals; no runtime allocation allowed)
__device__ float d_g[33554432];     // [N][A][HW]   g_x conv output
__device__ float d_phif[33554432];  // [N][A][HW]   phi conv, full res
__device__ float d_phip[8388608];   // [N][A][1024] phi pooled
__device__ float d_theta[16777216]; // [N][C][1024] theta (pooled x)
__device__ float d_attn[4194304];   // [N][C][A]    cmat -> softmax in place

// ---------------------------------------------------------------------------
// Fused 1x1 conv for g and phi: for each n,
//   G[a,l]  = sum_c Wg[a,c] * X[c,l] + bg[a]
//   Pf[a,l] = sum_c Wp[a,c] * X[c,l] + bp[a]
// 64x64 tiles, BK=16, 256 threads, 4x4 per thread, X tile shared by both outputs.
// ---------------------------------------------------------------------------
__global__ __launch_bounds__(256) void conv_kernel(
    const float* __restrict__ x,
    const float* __restrict__ wg, const float* __restrict__ bg,
    const float* __restrict__ wp, const float* __restrict__ bp)
{
    const int n  = blockIdx.z;
    const int a0 = blockIdx.y * 64;
    const int l0 = blockIdx.x * 64;
    const float* X = x + (size_t)n * CC * HWD;

    __shared__ float Ag[16][64];
    __shared__ float Ap[16][64];
    __shared__ float Bs[16][64];

    const int t  = threadIdx.x;
    const int tx = t & 15;
    const int ty = t >> 4;
    const int lr = t >> 2;          // 0..63 (row for W tiles)
    const int lc = (t & 3) << 2;    // 0,4,8,12 (k chunk for W tiles)
    const int xr = t >> 4;          // 0..15 (k row for X tile)
    const int xc = (t & 15) << 2;   // 0..60 (l chunk for X tile)

    float accg[4][4] = {};
    float accp[4][4] = {};

    for (int k0 = 0; k0 < CC; k0 += 16) {
        float4 vg = *(const float4*)(wg + (size_t)(a0 + lr) * CC + k0 + lc);
        float4 vp = *(const float4*)(wp + (size_t)(a0 + lr) * CC + k0 + lc);
        Ag[lc + 0][lr] = vg.x; Ag[lc + 1][lr] = vg.y;
        Ag[lc + 2][lr] = vg.z; Ag[lc + 3][lr] = vg.w;
        Ap[lc + 0][lr] = vp.x; Ap[lc + 1][lr] = vp.y;
        Ap[lc + 2][lr] = vp.z; Ap[lc + 3][lr] = vp.w;
        float4 vx = *(const float4*)(X + (size_t)(k0 + xr) * HWD + l0 + xc);
        *(float4*)&Bs[xr][xc] = vx;
        __syncthreads();
        #pragma unroll
        for (int kk = 0; kk < 16; ++kk) {
            float4 b4 = *(const float4*)&Bs[kk][tx * 4];
            float4 g4 = *(const float4*)&Ag[kk][ty * 4];
            float4 p4 = *(const float4*)&Ap[kk][ty * 4];
            float bb[4] = {b4.x, b4.y, b4.z, b4.w};
            float gg[4] = {g4.x, g4.y, g4.z, g4.w};
            float pp[4] = {p4.x, p4.y, p4.z, p4.w};
            #pragma unroll
            for (int i = 0; i < 4; ++i)
                #pragma unroll
                for (int j = 0; j < 4; ++j) {
                    accg[i][j] = fmaf(gg[i], bb[j], accg[i][j]);
                    accp[i][j] = fmaf(pp[i], bb[j], accp[i][j]);
                }
        }
        __syncthreads();
    }

    #pragma unroll
    for (int i = 0; i < 4; ++i) {
        const int a = a0 + ty * 4 + i;
        const float bgv = bg[a];
        const float bpv = bp[a];
        const size_t base = ((size_t)n * AA + a) * HWD + l0 + tx * 4;
        float4 og = make_float4(accg[i][0] + bgv, accg[i][1] + bgv,
                                accg[i][2] + bgv, accg[i][3] + bgv);
        float4 op = make_float4(accp[i][0] + bpv, accp[i][1] + bpv,
                                accp[i][2] + bpv, accp[i][3] + bpv);
        *(float4*)(d_g + base)    = og;
        *(float4*)(d_phif + base) = op;
    }
}

// ---------------------------------------------------------------------------
// 2x2 max pools
// ---------------------------------------------------------------------------
__global__ __launch_bounds__(256) void pool_theta_kernel(const float* __restrict__ x)
{
    const size_t idx = (size_t)blockIdx.x * 256 + threadIdx.x; // over N*C*1024
    if (idx >= (size_t)NB * CC * PHW) return;
    const int m = (int)(idx & 1023);
    const size_t nc = idx >> 10;
    const int r = m >> 5, wq = m & 31;
    const float* p = x + nc * HWD + (size_t)(r * 2) * WW + wq * 2;
    d_theta[idx] = fmaxf(fmaxf(p[0], p[1]), fmaxf(p[WW], p[WW + 1]));
}

__global__ __launch_bounds__(256) void pool_phi_kernel()
{
    const size_t idx = (size_t)blockIdx.x * 256 + threadIdx.x; // over N*A*1024
    if (idx >= (size_t)NB * AA * PHW) return;
    const int m = (int)(idx & 1023);
    const size_t na = idx >> 10;
    const int r = m >> 5, wq = m & 31;
    const float* p = d_phif + na * HWD + (size_t)(r * 2) * WW + wq * 2;
    d_phip[idx] = fmaxf(fmaxf(p[0], p[1]), fmaxf(p[WW], p[WW + 1]));
}

// ---------------------------------------------------------------------------
// cmat[n,c,a] = sum_m theta[n,c,m] * phi[n,a,m]   (NT GEMM, K=1024)
// ---------------------------------------------------------------------------
__global__ __launch_bounds__(256) void cmat_kernel()
{
    const int n  = blockIdx.z;
    const int c0 = blockIdx.y * 64;
    const int a0 = blockIdx.x * 64;
    const float* T = d_theta + (size_t)n * CC * PHW;
    const float* P = d_phip  + (size_t)n * AA * PHW;

    __shared__ float As[16][64];
    __shared__ float Bs[16][64];

    const int t  = threadIdx.x;
    const int tx = t & 15;
    const int ty = t >> 4;
    const int lr = t >> 2;
    const int lc = (t & 3) << 2;

    float acc[4][4] = {};

    for (int k0 = 0; k0 < PHW; k0 += 16) {
        float4 va = *(const float4*)(T + (size_t)(c0 + lr) * PHW + k0 + lc);
        float4 vb = *(const float4*)(P + (size_t)(a0 + lr) * PHW + k0 + lc);
        As[lc + 0][lr] = va.x; As[lc + 1][lr] = va.y;
        As[lc + 2][lr] = va.z; As[lc + 3][lr] = va.w;
        Bs[lc + 0][lr] = vb.x; Bs[lc + 1][lr] = vb.y;
        Bs[lc + 2][lr] = vb.z; Bs[lc + 3][lr] = vb.w;
        __syncthreads();
        #pragma unroll
        for (int kk = 0; kk < 16; ++kk) {
            float4 a4 = *(const float4*)&As[kk][ty * 4];
            float4 b4 = *(const float4*)&Bs[kk][tx * 4];
            float aa[4] = {a4.x, a4.y, a4.z, a4.w};
            float bb[4] = {b4.x, b4.y, b4.z, b4.w};
            #pragma unroll
            for (int i = 0; i < 4; ++i)
                #pragma unroll
                for (int j = 0; j < 4; ++j)
                    acc[i][j] = fmaf(aa[i], bb[j], acc[i][j]);
        }
        __syncthreads();
    }

    #pragma unroll
    for (int i = 0; i < 4; ++i) {
        const size_t base = ((size_t)n * CC + c0 + ty * 4 + i) * AA + a0 + tx * 4;
        *(float4*)(d_attn + base) =
            make_float4(acc[i][0], acc[i][1], acc[i][2], acc[i][3]);
    }
}

// ---------------------------------------------------------------------------
// Softmax over A=256, one block (256 threads) per (n,c) row, in place.
// ---------------------------------------------------------------------------
__global__ __launch_bounds__(256) void softmax_kernel()
{
    const size_t row = blockIdx.x;
    float* p = d_attn + row * AA;
    const int t = threadIdx.x;
    float v = p[t];

    __shared__ float red[8];
    float m = v;
    #pragma unroll
    for (int o = 16; o > 0; o >>= 1)
        m = fmaxf(m, __shfl_xor_sync(0xffffffffu, m, o));
    if ((t & 31) == 0) red[t >> 5] = m;
    __syncthreads();
    m = red[0];
    #pragma unroll
    for (int i = 1; i < 8; ++i) m = fmaxf(m, red[i]);
    __syncthreads();

    const float e = expf(v - m);
    float s = e;
    #pragma unroll
    for (int o = 16; o > 0; o >>= 1)
        s += __shfl_xor_sync(0xffffffffu, s, o);
    if ((t & 31) == 0) red[t >> 5] = s;
    __syncthreads();
    s = 0.f;
    #pragma unroll
    for (int i = 0; i < 8; ++i) s += red[i];

    p[t] = e / s;
}

// ---------------------------------------------------------------------------
// y[n,c,l] = sum_a attn[n,c,a] * g[n,a,l] + x[n,c,l]   (NN GEMM, K=256)
// ---------------------------------------------------------------------------
__global__ __launch_bounds__(256) void final_kernel(
    const float* __restrict__ x, float* __restrict__ out)
{
    const int n  = blockIdx.z;
    const int c0 = blockIdx.y * 64;
    const int l0 = blockIdx.x * 64;
    const float* Am = d_attn + (size_t)n * CC * AA;  // [c][a]
    const float* B  = d_g    + (size_t)n * AA * HWD; // [a][l]

    __shared__ float As[16][64];
    __shared__ float Bs[16][64];

    const int t  = threadIdx.x;
    const int tx = t & 15;
    const int ty = t >> 4;
    const int lr = t >> 2;
    const int lc = (t & 3) << 2;
    const int xr = t >> 4;
    const int xc = (t & 15) << 2;

    float acc[4][4] = {};

    for (int k0 = 0; k0 < AA; k0 += 16) {
        float4 va = *(const float4*)(Am + (size_t)(c0 + lr) * AA + k0 + lc);
        As[lc + 0][lr] = va.x; As[lc + 1][lr] = va.y;
        As[lc + 2][lr] = va.z; As[lc + 3][lr] = va.w;
        float4 vb = *(const float4*)(B + (size_t)(k0 + xr) * HWD + l0 + xc);
        *(float4*)&Bs[xr][xc] = vb;
        __syncthreads();
        #pragma unroll
        for (int kk = 0; kk < 16; ++kk) {
            float4 a4 = *(const float4*)&As[kk][ty * 4];
            float4 b4 = *(const float4*)&Bs[kk][tx * 4];
            float aa[4] = {a4.x, a4.y, a4.z, a4.w};
            float bb[4] = {b4.x, b4.y, b4.z, b4.w};
            #pragma unroll
            for (int i = 0; i < 4; ++i)
                #pragma unroll
                for (int j = 0; j < 4; ++j)
                    acc[i][j] = fmaf(aa[i], bb[j], acc[i][j]);
        }
        __syncthreads();
    }

    #pragma unroll
    for (int i = 0; i < 4; ++i) {
        const size_t base = ((size_t)n * CC + c0 + ty * 4 + i) * HWD + l0 + tx * 4;
        float4 xv = *(const float4*)(x + base);
        *(float4*)(out + base) = make_float4(acc[i][0] + xv.x, acc[i][1] + xv.y,
                                             acc[i][2] + xv.z, acc[i][3] + xv.w);
    }
}

extern "C" void kernel_launch(void* const* d_in, const int* in_sizes, int n_in,
                              void* d_out, int out_size)
{
    (void)in_sizes; (void)n_in; (void)out_size;
    const float* x  = (const float*)d_in[0];
    const float* wg = (const float*)d_in[1];
    const float* bg = (const float*)d_in[2];
    const float* wp = (const float*)d_in[3];
    const float* bp = (const float*)d_in[4];
    float* out = (float*)d_out;

    conv_kernel<<<dim3(HWD / 64, AA / 64, NB), 256>>>(x, wg, bg, wp, bp);

    {
        const size_t tt = (size_t)NB * CC * PHW;
        pool_theta_kernel<<<(unsigned)((tt + 255) / 256), 256>>>(x);
        const size_t tp = (size_t)NB * AA * PHW;
        pool_phi_kernel<<<(unsigned)((tp + 255) / 256), 256>>>();
    }

    cmat_kernel<<<dim3(AA / 64, CC / 64, NB), 256>>>();
    softmax_kernel<<<NB * CC, 256>>>();
    final_kernel<<<dim3(HWD / 64, CC / 64, NB), 256>>>(x, out);
}

// round 2
// speedup vs baseline: 1.4173x; 1.4173x over previous
#include <cuda_runtime.h>

#define NB 32
#define CC 512
#define AA 256
#define HH 64
#define WW 64
#define HWD 4096
#define PHW 1024

typedef unsigned long long u64;

// Scratch (static device globals; no runtime allocation allowed)
__device__ float d_g[33554432];     // [N][A][HW]   g_x conv output
__device__ float d_phif[33554432];  // [N][A][HW]   phi conv, full res
__device__ float d_phip[8388608];   // [N][A][1024] phi pooled
__device__ float d_theta[16777216]; // [N][C][1024] theta (pooled x)
__device__ float d_attn[4194304];   // [N][C][A]    cmat -> softmax in place

// ---- packed fp32x2 helpers (Blackwell) -----------------------------------
__device__ __forceinline__ u64 pk2(float lo, float hi) {
    u64 r; asm("mov.b64 %0,{%1,%2};" : "=l"(r) : "f"(lo), "f"(hi)); return r;
}
__device__ __forceinline__ void fma2(u64& d, u64 a, u64 b) {
    asm("fma.rn.f32x2 %0,%1,%2,%0;" : "+l"(d) : "l"(a), "l"(b));
}
__device__ __forceinline__ u64 add2(u64 a, u64 b) {
    u64 r; asm("add.rn.f32x2 %0,%1,%2;" : "=l"(r) : "l"(a), "l"(b)); return r;
}

// ---------------------------------------------------------------------------
// Fused 1x1 conv for g and phi. Tile: 64 (a) x 128 (l), BK=16, 256 threads,
// per-thread 4x8 per output (two 4-col groups at tx*4 and 64+tx*4).
// ---------------------------------------------------------------------------
__global__ __launch_bounds__(256) void conv_kernel(
    const float* __restrict__ x,
    const float* __restrict__ wg, const float* __restrict__ bg,
    const float* __restrict__ wp, const float* __restrict__ bp)
{
    const int n  = blockIdx.z;
    const int a0 = blockIdx.y * 64;
    const int l0 = blockIdx.x * 128;
    const float* X = x + (size_t)n * CC * HWD;

    __shared__ float Ag[16][64];
    __shared__ float Ap[16][64];
    __shared__ float Bs[16][128];

    const int t  = threadIdx.x;
    const int tx = t & 15;
    const int ty = t >> 4;
    // loaders
    const int wr = t >> 2;          // 0..63 weight row (a)
    const int wk = (t & 3) << 2;    // k chunk 0,4,8,12
    const int xr = t >> 4;          // 0..15 k row
    const int xc = (t & 15) << 3;   // 0..120 l chunk (8 floats)

    const float* wgp = wg + (size_t)(a0 + wr) * CC + wk;
    const float* wpp = wp + (size_t)(a0 + wr) * CC + wk;
    const float* xp  = X + (size_t)xr * HWD + l0 + xc;

    u64 accg[4][4] = {};
    u64 accp[4][4] = {};

    // preload iter 0
    float4 pg = *(const float4*)(wgp);
    float4 pp = *(const float4*)(wpp);
    float4 px0 = *(const float4*)(xp);
    float4 px1 = *(const float4*)(xp + 4);
    {
        Ag[wk + 0][wr] = pg.x; Ag[wk + 1][wr] = pg.y; Ag[wk + 2][wr] = pg.z; Ag[wk + 3][wr] = pg.w;
        Ap[wk + 0][wr] = pp.x; Ap[wk + 1][wr] = pp.y; Ap[wk + 2][wr] = pp.z; Ap[wk + 3][wr] = pp.w;
        *(float4*)&Bs[xr][xc] = px0;
        *(float4*)&Bs[xr][xc + 4] = px1;
    }
    __syncthreads();

    const int iters = CC / 16;  // 32
    #pragma unroll 1
    for (int it = 0; it < iters; ++it) {
        if (it + 1 < iters) {
            const int k0 = (it + 1) * 16;
            pg  = *(const float4*)(wgp + k0);
            pp  = *(const float4*)(wpp + k0);
            px0 = *(const float4*)(xp + (size_t)k0 * HWD);
            px1 = *(const float4*)(xp + (size_t)k0 * HWD + 4);
        }
        #pragma unroll
        for (int kk = 0; kk < 16; ++kk) {
            float4 g4 = *(const float4*)&Ag[kk][ty * 4];
            float4 p4 = *(const float4*)&Ap[kk][ty * 4];
            ulonglong2 b0 = *(const ulonglong2*)&Bs[kk][tx * 4];
            ulonglong2 b1 = *(const ulonglong2*)&Bs[kk][64 + tx * 4];
            u64 b[4] = {b0.x, b0.y, b1.x, b1.y};
            float ga[4] = {g4.x, g4.y, g4.z, g4.w};
            float pa[4] = {p4.x, p4.y, p4.z, p4.w};
            #pragma unroll
            for (int i = 0; i < 4; ++i) {
                u64 gd = pk2(ga[i], ga[i]);
                u64 pd = pk2(pa[i], pa[i]);
                #pragma unroll
                for (int j = 0; j < 4; ++j) {
                    fma2(accg[i][j], gd, b[j]);
                    fma2(accp[i][j], pd, b[j]);
                }
            }
        }
        __syncthreads();
        if (it + 1 < iters) {
            Ag[wk + 0][wr] = pg.x; Ag[wk + 1][wr] = pg.y; Ag[wk + 2][wr] = pg.z; Ag[wk + 3][wr] = pg.w;
            Ap[wk + 0][wr] = pp.x; Ap[wk + 1][wr] = pp.y; Ap[wk + 2][wr] = pp.z; Ap[wk + 3][wr] = pp.w;
            *(float4*)&Bs[xr][xc] = px0;
            *(float4*)&Bs[xr][xc + 4] = px1;
            __syncthreads();
        }
    }

    #pragma unroll
    for (int i = 0; i < 4; ++i) {
        const int a = a0 + ty * 4 + i;
        const u64 bg2 = pk2(bg[a], bg[a]);
        const u64 bp2 = pk2(bp[a], bp[a]);
        const size_t base = ((size_t)n * AA + a) * HWD + l0;
        ulonglong2 og0, og1, op0, op1;
        og0.x = add2(accg[i][0], bg2); og0.y = add2(accg[i][1], bg2);
        og1.x = add2(accg[i][2], bg2); og1.y = add2(accg[i][3], bg2);
        op0.x = add2(accp[i][0], bp2); op0.y = add2(accp[i][1], bp2);
        op1.x = add2(accp[i][2], bp2); op1.y = add2(accp[i][3], bp2);
        *(ulonglong2*)(d_g + base + tx * 4)        = og0;
        *(ulonglong2*)(d_g + base + 64 + tx * 4)   = og1;
        *(ulonglong2*)(d_phif + base + tx * 4)      = op0;
        *(ulonglong2*)(d_phif + base + 64 + tx * 4) = op1;
    }
}

// ---------------------------------------------------------------------------
// 2x2 max pools
// ---------------------------------------------------------------------------
__global__ __launch_bounds__(256) void pool_theta_kernel(const float* __restrict__ x)
{
    const size_t idx = (size_t)blockIdx.x * 256 + threadIdx.x;
    if (idx >= (size_t)NB * CC * PHW) return;
    const int m = (int)(idx & 1023);
    const size_t nc = idx >> 10;
    const int r = m >> 5, wq = m & 31;
    const float* p = x + nc * HWD + (size_t)(r * 2) * WW + wq * 2;
    d_theta[idx] = fmaxf(fmaxf(p[0], p[1]), fmaxf(p[WW], p[WW + 1]));
}

__global__ __launch_bounds__(256) void pool_phi_kernel()
{
    const size_t idx = (size_t)blockIdx.x * 256 + threadIdx.x;
    if (idx >= (size_t)NB * AA * PHW) return;
    const int m = (int)(idx & 1023);
    const size_t na = idx >> 10;
    const int r = m >> 5, wq = m & 31;
    const float* p = d_phif + na * HWD + (size_t)(r * 2) * WW + wq * 2;
    d_phip[idx] = fmaxf(fmaxf(p[0], p[1]), fmaxf(p[WW], p[WW + 1]));
}

// ---------------------------------------------------------------------------
// cmat[n,c,a] = sum_m theta[n,c,m] * phi[n,a,m]  (NT, K=1024)
// 128x128 tile, BK=16, 256 threads, 8x8 per thread (split 4+4 groups).
// ---------------------------------------------------------------------------
__global__ __launch_bounds__(256) void cmat_kernel()
{
    const int n  = blockIdx.z;
    const int c0 = blockIdx.y * 128;
    const int a0 = blockIdx.x * 128;
    const float* T = d_theta + (size_t)n * CC * PHW;
    const float* P = d_phip  + (size_t)n * AA * PHW;

    __shared__ float As[16][128];
    __shared__ float Bs[16][128];

    const int t  = threadIdx.x;
    const int tx = t & 15;
    const int ty = t >> 4;
    const int lr = t >> 1;          // 0..127
    const int lk = (t & 1) << 3;    // 0 or 8

    const float* tp = T + (size_t)(c0 + lr) * PHW + lk;
    const float* pp = P + (size_t)(a0 + lr) * PHW + lk;

    u64 acc[8][4] = {};

    float4 a0v = *(const float4*)(tp);
    float4 a1v = *(const float4*)(tp + 4);
    float4 b0v = *(const float4*)(pp);
    float4 b1v = *(const float4*)(pp + 4);
    {
        #pragma unroll
        for (int j = 0; j < 4; ++j) {
            As[lk + j][lr] = ((const float*)&a0v)[j];
            As[lk + 4 + j][lr] = ((const float*)&a1v)[j];
            Bs[lk + j][lr] = ((const float*)&b0v)[j];
            Bs[lk + 4 + j][lr] = ((const float*)&b1v)[j];
        }
    }
    __syncthreads();

    const int iters = PHW / 16;  // 64
    #pragma unroll 1
    for (int it = 0; it < iters; ++it) {
        if (it + 1 < iters) {
            const int k0 = (it + 1) * 16;
            a0v = *(const float4*)(tp + k0);
            a1v = *(const float4*)(tp + k0 + 4);
            b0v = *(const float4*)(pp + k0);
            b1v = *(const float4*)(pp + k0 + 4);
        }
        #pragma unroll
        for (int kk = 0; kk < 16; ++kk) {
            float4 af0 = *(const float4*)&As[kk][ty * 4];
            float4 af1 = *(const float4*)&As[kk][64 + ty * 4];
            ulonglong2 bf0 = *(const ulonglong2*)&Bs[kk][tx * 4];
            ulonglong2 bf1 = *(const ulonglong2*)&Bs[kk][64 + tx * 4];
            u64 b[4] = {bf0.x, bf0.y, bf1.x, bf1.y};
            float a[8] = {af0.x, af0.y, af0.z, af0.w, af1.x, af1.y, af1.z, af1.w};
            #pragma unroll
            for (int i = 0; i < 8; ++i) {
                u64 ad = pk2(a[i], a[i]);
                #pragma unroll
                for (int j = 0; j < 4; ++j) fma2(acc[i][j], ad, b[j]);
            }
        }
        __syncthreads();
        if (it + 1 < iters) {
            #pragma unroll
            for (int j = 0; j < 4; ++j) {
                As[lk + j][lr] = ((const float*)&a0v)[j];
                As[lk + 4 + j][lr] = ((const float*)&a1v)[j];
                Bs[lk + j][lr] = ((const float*)&b0v)[j];
                Bs[lk + 4 + j][lr] = ((const float*)&b1v)[j];
            }
            __syncthreads();
        }
    }

    #pragma unroll
    for (int ig = 0; ig < 2; ++ig)
        #pragma unroll
        for (int i = 0; i < 4; ++i) {
            const int r = ig * 64 + ty * 4 + i;
            float* dst = d_attn + ((size_t)n * CC + c0 + r) * AA + a0;
            ulonglong2 v0, v1;
            v0.x = acc[ig * 4 + i][0]; v0.y = acc[ig * 4 + i][1];
            v1.x = acc[ig * 4 + i][2]; v1.y = acc[ig * 4 + i][3];
            *(ulonglong2*)(dst + tx * 4)      = v0;
            *(ulonglong2*)(dst + 64 + tx * 4) = v1;
        }
}

// ---------------------------------------------------------------------------
// Softmax over A=256, one block per (n,c) row, in place.
// ---------------------------------------------------------------------------
__global__ __launch_bounds__(256) void softmax_kernel()
{
    const size_t row = blockIdx.x;
    float* p = d_attn + row * AA;
    const int t = threadIdx.x;
    float v = p[t];

    __shared__ float red[8];
    float m = v;
    #pragma unroll
    for (int o = 16; o > 0; o >>= 1)
        m = fmaxf(m, __shfl_xor_sync(0xffffffffu, m, o));
    if ((t & 31) == 0) red[t >> 5] = m;
    __syncthreads();
    m = red[0];
    #pragma unroll
    for (int i = 1; i < 8; ++i) m = fmaxf(m, red[i]);
    __syncthreads();

    const float e = expf(v - m);
    float s = e;
    #pragma unroll
    for (int o = 16; o > 0; o >>= 1)
        s += __shfl_xor_sync(0xffffffffu, s, o);
    if ((t & 31) == 0) red[t >> 5] = s;
    __syncthreads();
    s = 0.f;
    #pragma unroll
    for (int i = 0; i < 8; ++i) s += red[i];

    p[t] = e / s;
}

// ---------------------------------------------------------------------------
// y[n,c,l] = sum_a attn[n,c,a] * g[n,a,l] + x[n,c,l]  (NN, K=256)
// 128x128 tile, BK=16, 8x8 per thread.
// ---------------------------------------------------------------------------
__global__ __launch_bounds__(256) void final_kernel(
    const float* __restrict__ x, float* __restrict__ out)
{
    const int n  = blockIdx.z;
    const int c0 = blockIdx.y * 128;
    const int l0 = blockIdx.x * 128;
    const float* Am = d_attn + (size_t)n * CC * AA;
    const float* B  = d_g    + (size_t)n * AA * HWD;

    __shared__ float As[16][128];
    __shared__ float Bs[16][128];

    const int t  = threadIdx.x;
    const int tx = t & 15;
    const int ty = t >> 4;
    const int lr = t >> 1;
    const int lk = (t & 1) << 3;
    const int xr = t >> 4;
    const int xc = (t & 15) << 3;

    const float* ap = Am + (size_t)(c0 + lr) * AA + lk;
    const float* bp = B + (size_t)xr * HWD + l0 + xc;

    u64 acc[8][4] = {};

    float4 a0v = *(const float4*)(ap);
    float4 a1v = *(const float4*)(ap + 4);
    float4 b0v = *(const float4*)(bp);
    float4 b1v = *(const float4*)(bp + 4);
    {
        #pragma unroll
        for (int j = 0; j < 4; ++j) {
            As[lk + j][lr] = ((const float*)&a0v)[j];
            As[lk + 4 + j][lr] = ((const float*)&a1v)[j];
        }
        *(float4*)&Bs[xr][xc] = b0v;
        *(float4*)&Bs[xr][xc + 4] = b1v;
    }
    __syncthreads();

    const int iters = AA / 16;  // 16
    #pragma unroll 1
    for (int it = 0; it < iters; ++it) {
        if (it + 1 < iters) {
            const int k0 = (it + 1) * 16;
            a0v = *(const float4*)(ap + k0);
            a1v = *(const float4*)(ap + k0 + 4);
            b0v = *(const float4*)(bp + (size_t)k0 * HWD);
            b1v = *(const float4*)(bp + (size_t)k0 * HWD + 4);
        }
        #pragma unroll
        for (int kk = 0; kk < 16; ++kk) {
            float4 af0 = *(const float4*)&As[kk][ty * 4];
            float4 af1 = *(const float4*)&As[kk][64 + ty * 4];
            ulonglong2 bf0 = *(const ulonglong2*)&Bs[kk][tx * 4];
            ulonglong2 bf1 = *(const ulonglong2*)&Bs[kk][64 + tx * 4];
            u64 b[4] = {bf0.x, bf0.y, bf1.x, bf1.y};
            float a[8] = {af0.x, af0.y, af0.z, af0.w, af1.x, af1.y, af1.z, af1.w};
            #pragma unroll
            for (int i = 0; i < 8; ++i) {
                u64 ad = pk2(a[i], a[i]);
                #pragma unroll
                for (int j = 0; j < 4; ++j) fma2(acc[i][j], ad, b[j]);
            }
        }
        __syncthreads();
        if (it + 1 < iters) {
            #pragma unroll
            for (int j = 0; j < 4; ++j) {
                As[lk + j][lr] = ((const float*)&a0v)[j];
                As[lk + 4 + j][lr] = ((const float*)&a1v)[j];
            }
            *(float4*)&Bs[xr][xc] = b0v;
            *(float4*)&Bs[xr][xc + 4] = b1v;
            __syncthreads();
        }
    }

    #pragma unroll
    for (int ig = 0; ig < 2; ++ig)
        #pragma unroll
        for (int i = 0; i < 4; ++i) {
            const int r = ig * 64 + ty * 4 + i;
            const size_t base = ((size_t)n * CC + c0 + r) * HWD + l0;
            ulonglong2 xv0 = *(const ulonglong2*)(x + base + tx * 4);
            ulonglong2 xv1 = *(const ulonglong2*)(x + base + 64 + tx * 4);
            ulonglong2 v0, v1;
            v0.x = add2(acc[ig * 4 + i][0], xv0.x);
            v0.y = add2(acc[ig * 4 + i][1], xv0.y);
            v1.x = add2(acc[ig * 4 + i][2], xv1.x);
            v1.y = add2(acc[ig * 4 + i][3], xv1.y);
            *(ulonglong2*)(out + base + tx * 4)      = v0;
            *(ulonglong2*)(out + base + 64 + tx * 4) = v1;
        }
}

extern "C" void kernel_launch(void* const* d_in, const int* in_sizes, int n_in,
                              void* d_out, int out_size)
{
    (void)in_sizes; (void)n_in; (void)out_size;
    const float* x  = (const float*)d_in[0];
    const float* wg = (const float*)d_in[1];
    const float* bg = (const float*)d_in[2];
    const float* wp = (const float*)d_in[3];
    const float* bp = (const float*)d_in[4];
    float* out = (float*)d_out;

    conv_kernel<<<dim3(HWD / 128, AA / 64, NB), 256>>>(x, wg, bg, wp, bp);

    {
        const size_t tt = (size_t)NB * CC * PHW;
        pool_theta_kernel<<<(unsigned)((tt + 255) / 256), 256>>>(x);
        const size_t tp = (size_t)NB * AA * PHW;
        pool_phi_kernel<<<(unsigned)((tp + 255) / 256), 256>>>();
    }

    cmat_kernel<<<dim3(AA / 128, CC / 128, NB), 256>>>();
    softmax_kernel<<<NB * CC, 256>>>();
    final_kernel<<<dim3(HWD / 128, CC / 128, NB), 256>>>(x, out);
}

// round 5
// speedup vs baseline: 2.2054x; 1.5560x over previous
#include <cuda_runtime.h>
#include <cuda_bf16.h>
#include <cstdint>

#define NB 32
#define CCH 512
#define AA 256
#define HWD 4096
#define PHW 1024

typedef unsigned int u32;
typedef unsigned short u16;

// ---------------- scratch (static device globals) ---------------------------
__device__ __align__(16) u16 d_wh[262144], d_wl[262144];       // [512][512] rows 0-255 Wg, 256-511 Wphi
__device__ __align__(16) u16 d_gh[33554432], d_gl[33554432];   // [n][l][a]
__device__ float d_phif[33554432];                             // [n][a][l]
__device__ __align__(16) u16 d_thh[16777216], d_thl[16777216]; // [n][c][m]
__device__ __align__(16) u16 d_pph[8388608], d_ppl[8388608];   // [n][a][m]
__device__ float d_cm[4194304];                                // [n][c][a]
__device__ __align__(16) u16 d_ath[4194304], d_atl[4194304];   // [n][c][a]

// ---------------- helpers ---------------------------------------------------
__device__ __forceinline__ u32 smem_u32(const void* p) {
    u32 a;
    asm("{ .reg .u64 t; cvta.to.shared.u64 t, %1; cvt.u32.u64 %0, t; }" : "=r"(a) : "l"(p));
    return a;
}
__device__ __forceinline__ void cpa(u32 d, const void* s) {
    asm volatile("cp.async.cg.shared.global [%0],[%1],16;" :: "r"(d), "l"(s));
}
#define CPC      asm volatile("cp.async.commit_group;" ::: "memory")
#define CP_WAIT1 asm volatile("cp.async.wait_group 1;" ::: "memory")
#define CP_WAIT0 asm volatile("cp.async.wait_group 0;" ::: "memory")

__device__ __forceinline__ void ldsm4(unsigned f[4], u32 a) {
    asm volatile("ldmatrix.sync.aligned.m8n8.x4.shared.b16 {%0,%1,%2,%3},[%4];"
                 : "=r"(f[0]), "=r"(f[1]), "=r"(f[2]), "=r"(f[3]) : "r"(a));
}
__device__ __forceinline__ void mma16816(float c[4], const unsigned a[4], unsigned b0, unsigned b1) {
    asm volatile("mma.sync.aligned.m16n8k16.row.col.f32.bf16.bf16.f32 "
                 "{%0,%1,%2,%3},{%4,%5,%6,%7},{%8,%9},{%0,%1,%2,%3};"
                 : "+f"(c[0]), "+f"(c[1]), "+f"(c[2]), "+f"(c[3])
                 : "r"(a[0]), "r"(a[1]), "r"(a[2]), "r"(a[3]), "r"(b0), "r"(b1));
}
__device__ __forceinline__ void bsplit(float v, u16& h, u16& l) {
    __nv_bfloat16 bh = __float2bfloat16(v);
    h = __bfloat16_as_ushort(bh);
    l = __bfloat16_as_ushort(__float2bfloat16(v - __bfloat162float(bh)));
}
__device__ __forceinline__ void store_pair_split(u16* H, u16* L, size_t idx, float v0, float v1) {
    u16 h0, l0, h1, l1;
    bsplit(v0, h0, l0); bsplit(v1, h1, l1);
    *(u32*)(H + idx) = (u32)h0 | ((u32)h1 << 16);
    *(u32*)(L + idx) = (u32)l0 | ((u32)l1 << 16);
}
// ldmatrix fragment from 128B-pitch SW128-swizzled K-major tile
__device__ __forceinline__ void ldA128(unsigned f[4], u32 tb, int r0, int k0, int lane) {
    int row = r0 + (lane & 15);
    int ch = (k0 >> 3) + (lane >> 4);
    ldsm4(f, tb + row * 128 + (((ch ^ (row & 7)) & 7) << 4));
}
// ldmatrix fragment from 80B-pitch (32-k) tile, no swizzle (conflict-free by pitch)
__device__ __forceinline__ void ldA80(unsigned f[4], u32 tb, int r0, int k0, int lane) {
    int row = r0 + (lane & 15);
    int ch = (k0 >> 3) + (lane >> 4);
    ldsm4(f, tb + row * 80 + (ch << 4));
}
// cp.async stage of 128row x 64k bf16 tile (128B pitch, swizzled)
__device__ __forceinline__ void stage128(u32 dst, const u16* src, int ld, int t) {
    #pragma unroll
    for (int i = 0; i < 4; ++i) {
        int idx = t + i * 256;
        int row = idx >> 3, ch = idx & 7;
        cpa(dst + row * 128 + (((ch ^ (row & 7)) & 7) << 4), src + (size_t)row * ld + ch * 8);
    }
}
// cp.async stage of 128row x 32k bf16 tile (80B pitch), ld=512
__device__ __forceinline__ void stage80(u32 dst, const u16* src, int t) {
    #pragma unroll
    for (int i = 0; i < 2; ++i) {
        int idx = t + i * 256;
        int row = idx >> 2, ch = idx & 3;
        cpa(dst + row * 80 + (ch << 4), src + (size_t)row * 512 + ch * 8);
    }
}

// ===========================================================================
// split_w: Wg,Wphi -> bf16 hi/lo  [512][512]
// ===========================================================================
__global__ __launch_bounds__(256) void split_w_k(const float* __restrict__ wg,
                                                 const float* __restrict__ wp) {
    int idx = blockIdx.x * 256 + threadIdx.x;
    int r = idx >> 9, c = idx & 511;
    float v = (r < 256) ? wg[r * 512 + c] : wp[(r - 256) * 512 + c];
    u16 h, l; bsplit(v, h, l);
    d_wh[idx] = h; d_wl[idx] = l;
}

// ===========================================================================
// conv: G[l][a], Phi[a][l]  (M=l 128, N=a 128, K=c 512, BK=32, 2-stage)
// A = X^T staged through regs (fp32->bf16 hi/lo), B = pre-split W via cp.async
// ===========================================================================
#define CV_STG 61440
#define CV_SMEM (2 * CV_STG)
__global__ __launch_bounds__(256) void conv_mma(const float* __restrict__ x,
                                                const float* __restrict__ bg,
                                                const float* __restrict__ bp) {
    extern __shared__ char sm[];
    const u32 sb = smem_u32(sm);
    const int t = threadIdx.x, lane = t & 31;
    const int wm = (t >> 5) & 1, wn = t >> 6;
    const int nb = blockIdx.z, a0 = blockIdx.y * 128, l0 = blockIdx.x * 128;
    const float* X = x + (size_t)nb * CCH * HWD;

    float aG[4][4][4] = {};
    float aP[4][4][4] = {};
    float xv0[8], xv1[8];

    // buf offsets: Xh 0, Xl 10240, Gh 20480, Gl 30720, Ph 40960, Pl 51200
    {
        #pragma unroll
        for (int i = 0; i < 8; ++i) {
            int e = t + i * 256; int l = e & 127; int cp = e >> 7;
            xv0[i] = X[(size_t)(2 * cp) * HWD + l0 + l];
            xv1[i] = X[(size_t)(2 * cp + 1) * HWD + l0 + l];
        }
        stage80(sb + 20480, d_wh + (size_t)a0 * 512, t);
        stage80(sb + 30720, d_wl + (size_t)a0 * 512, t);
        stage80(sb + 40960, d_wh + (size_t)(256 + a0) * 512, t);
        stage80(sb + 51200, d_wl + (size_t)(256 + a0) * 512, t);
        CPC;
        #pragma unroll
        for (int i = 0; i < 8; ++i) {
            int e = t + i * 256; int l = e & 127; int cp = e >> 7;
            u16 h0, q0, h1, q1; bsplit(xv0[i], h0, q0); bsplit(xv1[i], h1, q1);
            *(u32*)(sm + l * 80 + cp * 4) = (u32)h0 | ((u32)h1 << 16);
            *(u32*)(sm + 10240 + l * 80 + cp * 4) = (u32)q0 | ((u32)q1 << 16);
        }
    }

    #pragma unroll 1
    for (int s = 0; s < 16; ++s) {
        const int buf = s & 1;
        char* nbuf = sm + (buf ^ 1) * CV_STG;
        const u32 nbu = sb + (buf ^ 1) * CV_STG;
        if (s + 1 < 16) {
            const int k0 = (s + 1) * 32;
            #pragma unroll
            for (int i = 0; i < 8; ++i) {
                int e = t + i * 256; int l = e & 127; int cp = e >> 7;
                xv0[i] = X[(size_t)(k0 + 2 * cp) * HWD + l0 + l];
                xv1[i] = X[(size_t)(k0 + 2 * cp + 1) * HWD + l0 + l];
            }
            stage80(nbu + 20480, d_wh + (size_t)a0 * 512 + k0, t);
            stage80(nbu + 30720, d_wl + (size_t)a0 * 512 + k0, t);
            stage80(nbu + 40960, d_wh + (size_t)(256 + a0) * 512 + k0, t);
            stage80(nbu + 51200, d_wl + (size_t)(256 + a0) * 512 + k0, t);
            CPC; CP_WAIT1;
        } else { CP_WAIT0; }
        __syncthreads();

        const u32 bu = sb + buf * CV_STG;
        #pragma unroll
        for (int ks = 0; ks < 2; ++ks) {
            const int k0 = ks * 16;
            unsigned ah[4][4], al[4][4];
            #pragma unroll
            for (int mt = 0; mt < 4; ++mt) {
                ldA80(ah[mt], bu, wm * 64 + mt * 16, k0, lane);
                ldA80(al[mt], bu + 10240, wm * 64 + mt * 16, k0, lane);
            }
            unsigned gh[2][4], gl[2][4], ph[2][4], pl[2][4];
            #pragma unroll
            for (int bt = 0; bt < 2; ++bt) {
                ldA80(gh[bt], bu + 20480, wn * 32 + bt * 16, k0, lane);
                ldA80(gl[bt], bu + 30720, wn * 32 + bt * 16, k0, lane);
                ldA80(ph[bt], bu + 40960, wn * 32 + bt * 16, k0, lane);
                ldA80(pl[bt], bu + 51200, wn * 32 + bt * 16, k0, lane);
            }
            #pragma unroll
            for (int mt = 0; mt < 4; ++mt)
                #pragma unroll
                for (int n8 = 0; n8 < 4; ++n8) {
                    const int bt = n8 >> 1, sl = n8 & 1;
                    mma16816(aG[mt][n8], ah[mt], gh[bt][sl], gh[bt][2 + sl]);
                    mma16816(aG[mt][n8], al[mt], gh[bt][sl], gh[bt][2 + sl]);
                    mma16816(aG[mt][n8], ah[mt], gl[bt][sl], gl[bt][2 + sl]);
                    mma16816(aP[mt][n8], ah[mt], ph[bt][sl], ph[bt][2 + sl]);
                    mma16816(aP[mt][n8], al[mt], ph[bt][sl], ph[bt][2 + sl]);
                    mma16816(aP[mt][n8], ah[mt], pl[bt][sl], pl[bt][2 + sl]);
                }
        }
        if (s + 1 < 16) {
            #pragma unroll
            for (int i = 0; i < 8; ++i) {
                int e = t + i * 256; int l = e & 127; int cp = e >> 7;
                u16 h0, q0, h1, q1; bsplit(xv0[i], h0, q0); bsplit(xv1[i], h1, q1);
                *(u32*)(nbuf + l * 80 + cp * 4) = (u32)h0 | ((u32)h1 << 16);
                *(u32*)(nbuf + 10240 + l * 80 + cp * 4) = (u32)q0 | ((u32)q1 << 16);
            }
        }
        __syncthreads();
    }

    // epilogue G -> d_gh/d_gl [l][a]
    #pragma unroll
    for (int mt = 0; mt < 4; ++mt)
        #pragma unroll
        for (int n8 = 0; n8 < 4; ++n8) {
            const int l = l0 + wm * 64 + mt * 16 + (lane >> 2);
            const int a = a0 + wn * 32 + n8 * 8 + ((lane & 3) << 1);
            const float b0 = __ldg(bg + a), b1 = __ldg(bg + a + 1);
            const size_t i0 = ((size_t)nb * HWD + l) * AA + a;
            store_pair_split(d_gh, d_gl, i0, aG[mt][n8][0] + b0, aG[mt][n8][1] + b1);
            store_pair_split(d_gh, d_gl, i0 + (size_t)8 * AA,
                             aG[mt][n8][2] + b0, aG[mt][n8][3] + b1);
        }
    // epilogue Phi: transpose via smem -> d_phif [a][l] fp32
    float* ts = (float*)sm;
    #pragma unroll
    for (int mt = 0; mt < 4; ++mt)
        #pragma unroll
        for (int n8 = 0; n8 < 4; ++n8) {
            const int nl = wn * 32 + n8 * 8 + ((lane & 3) << 1);
            const int ml = wm * 64 + mt * 16 + (lane >> 2);
            const float b0 = __ldg(bp + a0 + nl), b1 = __ldg(bp + a0 + nl + 1);
            ts[nl * 132 + ml] = aP[mt][n8][0] + b0;
            ts[(nl + 1) * 132 + ml] = aP[mt][n8][1] + b1;
            ts[nl * 132 + ml + 8] = aP[mt][n8][2] + b0;
            ts[(nl + 1) * 132 + ml + 8] = aP[mt][n8][3] + b1;
        }
    __syncthreads();
    #pragma unroll
    for (int i = 0; i < 16; ++i) {
        int e = t + i * 256; int row = e >> 5; int c4 = (e & 31) << 2;
        float4 v = *(float4*)&ts[row * 132 + c4];
        *(float4*)&d_phif[((size_t)nb * AA + a0 + row) * HWD + l0 + c4] = v;
    }
}

// ===========================================================================
// pools
// ===========================================================================
__global__ __launch_bounds__(256) void pool_theta_k(const float* __restrict__ x) {
    const size_t idx = (size_t)blockIdx.x * 256 + threadIdx.x;
    const int m = (int)(idx & 1023);
    const size_t nc = idx >> 10;
    const int r = m >> 5, w = m & 31;
    const float* p = x + nc * HWD + (size_t)(2 * r) * 64 + 2 * w;
    float v = fmaxf(fmaxf(p[0], p[1]), fmaxf(p[64], p[65]));
    u16 h, l; bsplit(v, h, l);
    d_thh[idx] = h; d_thl[idx] = l;
}
__global__ __launch_bounds__(256) void pool_phi_k() {
    const size_t idx = (size_t)blockIdx.x * 256 + threadIdx.x;
    const int m = (int)(idx & 1023);
    const size_t na = idx >> 10;
    const int r = m >> 5, w = m & 31;
    const float* p = d_phif + na * HWD + (size_t)(2 * r) * 64 + 2 * w;
    float v = fmaxf(fmaxf(p[0], p[1]), fmaxf(p[64], p[65]));
    u16 h, l; bsplit(v, h, l);
    d_pph[idx] = h; d_ppl[idx] = l;
}

// ===========================================================================
// cmat: cm[c][a] = theta[c][m] . phi[a][m], K=1024, BK=64, 2-stage
// ===========================================================================
#define CM_STG 65536
#define CM_SMEM (2 * CM_STG)
__global__ __launch_bounds__(256) void cmat_mma() {
    extern __shared__ char sm[];
    const u32 sb = smem_u32(sm);
    const int t = threadIdx.x, lane = t & 31;
    const int wm = (t >> 5) & 1, wn = t >> 6;
    const int nb = blockIdx.z, c0 = blockIdx.y * 128, a0b = blockIdx.x * 128;
    const u16* TH = d_thh + ((size_t)nb * CCH + c0) * PHW;
    const u16* TL = d_thl + ((size_t)nb * CCH + c0) * PHW;
    const u16* PH = d_pph + ((size_t)nb * AA + a0b) * PHW;
    const u16* PL = d_ppl + ((size_t)nb * AA + a0b) * PHW;

    float acc[4][4][4] = {};

    stage128(sb, TH, PHW, t);
    stage128(sb + 16384, TL, PHW, t);
    stage128(sb + 32768, PH, PHW, t);
    stage128(sb + 49152, PL, PHW, t);
    CPC;
    #pragma unroll 1
    for (int s = 0; s < 16; ++s) {
        const int buf = s & 1;
        if (s + 1 < 16) {
            const u32 nbu = sb + (buf ^ 1) * CM_STG;
            const int k0 = (s + 1) * 64;
            stage128(nbu, TH + k0, PHW, t);
            stage128(nbu + 16384, TL + k0, PHW, t);
            stage128(nbu + 32768, PH + k0, PHW, t);
            stage128(nbu + 49152, PL + k0, PHW, t);
            CPC; CP_WAIT1;
        } else { CP_WAIT0; }
        __syncthreads();
        const u32 bu = sb + buf * CM_STG;
        #pragma unroll
        for (int ks = 0; ks < 4; ++ks) {
            const int k0 = ks * 16;
            unsigned ah[4][4], al[4][4], bh[2][4], bl[2][4];
            #pragma unroll
            for (int mt = 0; mt < 4; ++mt) {
                ldA128(ah[mt], bu, wm * 64 + mt * 16, k0, lane);
                ldA128(al[mt], bu + 16384, wm * 64 + mt * 16, k0, lane);
            }
            #pragma unroll
            for (int bt = 0; bt < 2; ++bt) {
                ldA128(bh[bt], bu + 32768, wn * 32 + bt * 16, k0, lane);
                ldA128(bl[bt], bu + 49152, wn * 32 + bt * 16, k0, lane);
            }
            #pragma unroll
            for (int mt = 0; mt < 4; ++mt)
                #pragma unroll
                for (int n8 = 0; n8 < 4; ++n8) {
                    const int bt = n8 >> 1, sl = n8 & 1;
                    mma16816(acc[mt][n8], ah[mt], bh[bt][sl], bh[bt][2 + sl]);
                    mma16816(acc[mt][n8], al[mt], bh[bt][sl], bh[bt][2 + sl]);
                    mma16816(acc[mt][n8], ah[mt], bl[bt][sl], bl[bt][2 + sl]);
                }
        }
        __syncthreads();
    }
    #pragma unroll
    for (int mt = 0; mt < 4; ++mt)
        #pragma unroll
        for (int n8 = 0; n8 < 4; ++n8) {
            const int c = c0 + wm * 64 + mt * 16 + (lane >> 2);
            const int a = a0b + wn * 32 + n8 * 8 + ((lane & 3) << 1);
            float* dst = d_cm + ((size_t)nb * CCH + c) * AA + a;
            float2 v0; v0.x = acc[mt][n8][0]; v0.y = acc[mt][n8][1];
            float2 v1; v1.x = acc[mt][n8][2]; v1.y = acc[mt][n8][3];
            *(float2*)dst = v0;
            *(float2*)(dst + (size_t)8 * AA) = v1;
        }
}

// ===========================================================================
// softmax over a=256 rows, split result to bf16 hi/lo
// ===========================================================================
__global__ __launch_bounds__(256) void softmax_k() {
    const size_t row = blockIdx.x;
    const float* p = d_cm + row * AA;
    const int t = threadIdx.x;
    float v = p[t];
    __shared__ float red[8];
    float m = v;
    #pragma unroll
    for (int o = 16; o > 0; o >>= 1) m = fmaxf(m, __shfl_xor_sync(0xffffffffu, m, o));
    if ((t & 31) == 0) red[t >> 5] = m;
    __syncthreads();
    m = red[0];
    #pragma unroll
    for (int i = 1; i < 8; ++i) m = fmaxf(m, red[i]);
    __syncthreads();
    const float e = expf(v - m);
    float s = e;
    #pragma unroll
    for (int o = 16; o > 0; o >>= 1) s += __shfl_xor_sync(0xffffffffu, s, o);
    if ((t & 31) == 0) red[t >> 5] = s;
    __syncthreads();
    s = 0.f;
    #pragma unroll
    for (int i = 0; i < 8; ++i) s += red[i];
    float pr = e / s;
    u16 h, l; bsplit(pr, h, l);
    d_ath[row * AA + t] = h;
    d_atl[row * AA + t] = l;
}

// ===========================================================================
// final: out[c][l] = attn[c][a] . G[l][a] + x, K=256, BK=64, 2-stage
// ===========================================================================
__global__ __launch_bounds__(256) void final_mma(const float* __restrict__ x,
                                                 float* __restrict__ out) {
    extern __shared__ char sm[];
    const u32 sb = smem_u32(sm);
    const int t = threadIdx.x, lane = t & 31;
    const int wm = (t >> 5) & 1, wn = t >> 6;
    const int nb = blockIdx.z, c0 = blockIdx.y * 128, l0 = blockIdx.x * 128;
    const u16* AH = d_ath + ((size_t)nb * CCH + c0) * AA;
    const u16* AL = d_atl + ((size_t)nb * CCH + c0) * AA;
    const u16* BH = d_gh + ((size_t)nb * HWD + l0) * AA;
    const u16* BL = d_gl + ((size_t)nb * HWD + l0) * AA;

    float acc[4][4][4] = {};

    stage128(sb, AH, AA, t);
    stage128(sb + 16384, AL, AA, t);
    stage128(sb + 32768, BH, AA, t);
    stage128(sb + 49152, BL, AA, t);
    CPC;
    #pragma unroll 1
    for (int s = 0; s < 4; ++s) {
        const int buf = s & 1;
        if (s + 1 < 4) {
            const u32 nbu = sb + (buf ^ 1) * CM_STG;
            const int k0 = (s + 1) * 64;
            stage128(nbu, AH + k0, AA, t);
            stage128(nbu + 16384, AL + k0, AA, t);
            stage128(nbu + 32768, BH + k0, AA, t);
            stage128(nbu + 49152, BL + k0, AA, t);
            CPC; CP_WAIT1;
        } else { CP_WAIT0; }
        __syncthreads();
        const u32 bu = sb + buf * CM_STG;
        #pragma unroll
        for (int ks = 0; ks < 4; ++ks) {
            const int k0 = ks * 16;
            unsigned ah[4][4], al[4][4], bh[2][4], bl[2][4];
            #pragma unroll
            for (int mt = 0; mt < 4; ++mt) {
                ldA128(ah[mt], bu, wm * 64 + mt * 16, k0, lane);
                ldA128(al[mt], bu + 16384, wm * 64 + mt * 16, k0, lane);
            }
            #pragma unroll
            for (int bt = 0; bt < 2; ++bt) {
                ldA128(bh[bt], bu + 32768, wn * 32 + bt * 16, k0, lane);
                ldA128(bl[bt], bu + 49152, wn * 32 + bt * 16, k0, lane);
            }
            #pragma unroll
            for (int mt = 0; mt < 4; ++mt)
                #pragma unroll
                for (int n8 = 0; n8 < 4; ++n8) {
                    const int bt = n8 >> 1, sl = n8 & 1;
                    mma16816(acc[mt][n8], ah[mt], bh[bt][sl], bh[bt][2 + sl]);
                    mma16816(acc[mt][n8], al[mt], bh[bt][sl], bh[bt][2 + sl]);
                    mma16816(acc[mt][n8], ah[mt], bl[bt][sl], bl[bt][2 + sl]);
                }
        }
        __syncthreads();
    }
    #pragma unroll
    for (int mt = 0; mt < 4; ++mt)
        #pragma unroll
        for (int n8 = 0; n8 < 4; ++n8) {
            const int c = c0 + wm * 64 + mt * 16 + (lane >> 2);
            const int l = l0 + wn * 32 + n8 * 8 + ((lane & 3) << 1);
            size_t i0 = ((size_t)nb * CCH + c) * HWD + l;
            float2 xv = *(const float2*)(x + i0);
            float2 o0; o0.x = acc[mt][n8][0] + xv.x; o0.y = acc[mt][n8][1] + xv.y;
            *(float2*)(out + i0) = o0;
            i0 += (size_t)8 * HWD;
            float2 xw = *(const float2*)(x + i0);
            float2 o1; o1.x = acc[mt][n8][2] + xw.x; o1.y = acc[mt][n8][3] + xw.y;
            *(float2*)(out + i0) = o1;
        }
}

// ===========================================================================
extern "C" void kernel_launch(void* const* d_in, const int* in_sizes, int n_in,
                              void* d_out, int out_size) {
    (void)in_sizes; (void)n_in; (void)out_size;
    const float* x  = (const float*)d_in[0];
    const float* wg = (const float*)d_in[1];
    const float* bg = (const float*)d_in[2];
    const float* wp = (const float*)d_in[3];
    const float* bp = (const float*)d_in[4];
    float* out = (float*)d_out;

    cudaFuncSetAttribute(conv_mma,  cudaFuncAttributeMaxDynamicSharedMemorySize, CV_SMEM);
    cudaFuncSetAttribute(cmat_mma,  cudaFuncAttributeMaxDynamicSharedMemorySize, CM_SMEM);
    cudaFuncSetAttribute(final_mma, cudaFuncAttributeMaxDynamicSharedMemorySize, CM_SMEM);

    split_w_k<<<1024, 256>>>(wg, wp);
    pool_theta_k<<<(unsigned)(((size_t)NB * CCH * PHW) / 256), 256>>>(x);

    conv_mma<<<dim3(32, 2, NB), 256, CV_SMEM>>>(x, bg, bp);

    pool_phi_k<<<(unsigned)(((size_t)NB * AA * PHW) / 256), 256>>>();

    cmat_mma<<<dim3(2, 4, NB), 256, CM_SMEM>>>();
    softmax_k<<<NB * CCH, 256>>>();

    final_mma<<<dim3(32, 4, NB), 256, CM_SMEM>>>(x, out);
}

// round 6
// speedup vs baseline: 2.9738x; 1.3484x over previous
#include <cuda_runtime.h>
#include <cuda_fp16.h>
#include <cstdint>

#define NB 32
#define CCH 512
#define AA 256
#define HWD 4096
#define PHW 1024

typedef unsigned int u32;
typedef unsigned short u16;

// ---------------- scratch (static device globals) ---------------------------
__device__ __align__(16) u16 d_wh[262144], d_wl[262144];       // [512][512] rows 0-255 Wg, 256-511 Wphi (x64 scaled)
__device__ __align__(16) u16 d_gh[33554432];                   // [n][l][a] fp16 single
__device__ __align__(16) u16 d_thh[16777216], d_thl[16777216]; // [n][c][m]
__device__ __align__(16) u16 d_pph[8388608], d_ppl[8388608];   // [n][a][m]
__device__ __align__(16) u16 d_ath[4194304], d_atl[4194304];   // [n][c][a]

// ---------------- helpers ---------------------------------------------------
__device__ __forceinline__ u32 smem_u32(const void* p) {
    u32 a;
    asm("{ .reg .u64 t; cvta.to.shared.u64 t, %1; cvt.u32.u64 %0, t; }" : "=r"(a) : "l"(p));
    return a;
}
__device__ __forceinline__ void cpa(u32 d, const void* s) {
    asm volatile("cp.async.cg.shared.global [%0],[%1],16;" :: "r"(d), "l"(s));
}
#define CPC      asm volatile("cp.async.commit_group;" ::: "memory")
#define CP_WAIT1 asm volatile("cp.async.wait_group 1;" ::: "memory")
#define CP_WAIT0 asm volatile("cp.async.wait_group 0;" ::: "memory")

__device__ __forceinline__ void ldsm4(unsigned f[4], u32 a) {
    asm volatile("ldmatrix.sync.aligned.m8n8.x4.shared.b16 {%0,%1,%2,%3},[%4];"
                 : "=r"(f[0]), "=r"(f[1]), "=r"(f[2]), "=r"(f[3]) : "r"(a));
}
__device__ __forceinline__ void mma16816(float c[4], const unsigned a[4], unsigned b0, unsigned b1) {
    asm volatile("mma.sync.aligned.m16n8k16.row.col.f32.f16.f16.f32 "
                 "{%0,%1,%2,%3},{%4,%5,%6,%7},{%8,%9},{%0,%1,%2,%3};"
                 : "+f"(c[0]), "+f"(c[1]), "+f"(c[2]), "+f"(c[3])
                 : "r"(a[0]), "r"(a[1]), "r"(a[2]), "r"(a[3]), "r"(b0), "r"(b1));
}
__device__ __forceinline__ void hsplit(float v, u16& h, u16& l) {
    __half hh = __float2half_rn(v);
    h = __half_as_ushort(hh);
    l = __half_as_ushort(__float2half_rn(v - __half2float(hh)));
}
__device__ __forceinline__ u16 h1(float v) { return __half_as_ushort(__float2half_rn(v)); }

// ldmatrix fragment from 128B-pitch SW128-swizzled K-major tile
__device__ __forceinline__ void ldA128(unsigned f[4], u32 tb, int r0, int k0, int lane) {
    int row = r0 + (lane & 15);
    int ch = (k0 >> 3) + (lane >> 4);
    ldsm4(f, tb + row * 128 + (((ch ^ (row & 7)) & 7) << 4));
}
// ldmatrix fragment from 80B-pitch (32-k) tile, no swizzle
__device__ __forceinline__ void ldA80(unsigned f[4], u32 tb, int r0, int k0, int lane) {
    int row = r0 + (lane & 15);
    int ch = (k0 >> 3) + (lane >> 4);
    ldsm4(f, tb + row * 80 + (ch << 4));
}
// cp.async stage of 128row x 32k fp16 tile (80B pitch), ld=512 (for W)
__device__ __forceinline__ void stage80(u32 dst, const u16* src, int t) {
    #pragma unroll
    for (int i = 0; i < 2; ++i) {
        int idx = t + i * 256;
        int row = idx >> 2, ch = idx & 3;
        cpa(dst + row * 80 + (ch << 4), src + (size_t)row * 512 + ch * 8);
    }
}

// ===========================================================================
// split_w: (Wg,Wphi)*64 -> fp16 hi/lo  [512][512]
// ===========================================================================
__global__ __launch_bounds__(256) void split_w_k(const float* __restrict__ wg,
                                                 const float* __restrict__ wp) {
    int idx = blockIdx.x * 256 + threadIdx.x;
    int r = idx >> 9, c = idx & 511;
    float v = ((r < 256) ? wg[r * 512 + c] : wp[(r - 256) * 512 + c]) * 64.0f;
    u16 h, l; hsplit(v, h, l);
    d_wh[idx] = h; d_wl[idx] = l;
}

// ===========================================================================
// pool_theta: 2x2 max of x -> fp16 hi/lo
// ===========================================================================
__global__ __launch_bounds__(256) void pool_theta_k(const float* __restrict__ x) {
    const size_t idx = (size_t)blockIdx.x * 256 + threadIdx.x;
    const int m = (int)(idx & 1023);
    const size_t nc = idx >> 10;
    const int r = m >> 5, w = m & 31;
    const float* p = x + nc * HWD + (size_t)(2 * r) * 64 + 2 * w;
    float v = fmaxf(fmaxf(p[0], p[1]), fmaxf(p[64], p[65]));
    u16 h, l; hsplit(v, h, l);
    d_thh[idx] = h; d_thl[idx] = l;
}

// ===========================================================================
// conv: G[l][a] fp16 (2-term), phi -> pooled fp16 hi/lo (3-term + fused 2x2 pool)
// M=l 128, N=a 128, K=c 512, BK=32, 2-stage.
// buf: Xh 0, Xl 10240, Gh 20480, Ph 30720, Pl 40960   (CV_STG=51200)
// ===========================================================================
#define CV_STG 51200
#define CV_SMEM (2 * CV_STG)
__global__ __launch_bounds__(256) void conv_mma(const float* __restrict__ x,
                                                const float* __restrict__ bg,
                                                const float* __restrict__ bp) {
    extern __shared__ char sm[];
    const u32 sb = smem_u32(sm);
    const int t = threadIdx.x, lane = t & 31;
    const int wm = (t >> 5) & 1, wn = t >> 6;
    const int nb = blockIdx.z, a0 = blockIdx.y * 128, l0 = blockIdx.x * 128;
    const float* X = x + (size_t)nb * CCH * HWD;

    float aG[4][4][4] = {};
    float aP[4][4][4] = {};
    float xv0[8], xv1[8];

    {
        #pragma unroll
        for (int i = 0; i < 8; ++i) {
            int e = t + i * 256; int l = e & 127; int cp = e >> 7;
            xv0[i] = X[(size_t)(2 * cp) * HWD + l0 + l];
            xv1[i] = X[(size_t)(2 * cp + 1) * HWD + l0 + l];
        }
        stage80(sb + 20480, d_wh + (size_t)a0 * 512, t);
        stage80(sb + 30720, d_wh + (size_t)(256 + a0) * 512, t);
        stage80(sb + 40960, d_wl + (size_t)(256 + a0) * 512, t);
        CPC;
        #pragma unroll
        for (int i = 0; i < 8; ++i) {
            int e = t + i * 256; int l = e & 127; int cp = e >> 7;
            u16 h0, q0, h1, q1; hsplit(xv0[i], h0, q0); hsplit(xv1[i], h1, q1);
            *(u32*)(sm + l * 80 + cp * 4) = (u32)h0 | ((u32)h1 << 16);
            *(u32*)(sm + 10240 + l * 80 + cp * 4) = (u32)q0 | ((u32)q1 << 16);
        }
    }

    #pragma unroll 1
    for (int s = 0; s < 16; ++s) {
        const int buf = s & 1;
        char* nbuf = sm + (buf ^ 1) * CV_STG;
        const u32 nbu = sb + (buf ^ 1) * CV_STG;
        if (s + 1 < 16) {
            const int k0 = (s + 1) * 32;
            #pragma unroll
            for (int i = 0; i < 8; ++i) {
                int e = t + i * 256; int l = e & 127; int cp = e >> 7;
                xv0[i] = X[(size_t)(k0 + 2 * cp) * HWD + l0 + l];
                xv1[i] = X[(size_t)(k0 + 2 * cp + 1) * HWD + l0 + l];
            }
            stage80(nbu + 20480, d_wh + (size_t)a0 * 512 + k0, t);
            stage80(nbu + 30720, d_wh + (size_t)(256 + a0) * 512 + k0, t);
            stage80(nbu + 40960, d_wl + (size_t)(256 + a0) * 512 + k0, t);
            CPC; CP_WAIT1;
        } else { CP_WAIT0; }
        __syncthreads();

        const u32 bu = sb + buf * CV_STG;
        #pragma unroll
        for (int ks = 0; ks < 2; ++ks) {
            const int k0 = ks * 16;
            unsigned ah[4][4], al[4][4];
            #pragma unroll
            for (int mt = 0; mt < 4; ++mt) {
                ldA80(ah[mt], bu, wm * 64 + mt * 16, k0, lane);
                ldA80(al[mt], bu + 10240, wm * 64 + mt * 16, k0, lane);
            }
            unsigned gh[2][4], ph[2][4], pl[2][4];
            #pragma unroll
            for (int bt = 0; bt < 2; ++bt) {
                ldA80(gh[bt], bu + 20480, wn * 32 + bt * 16, k0, lane);
                ldA80(ph[bt], bu + 30720, wn * 32 + bt * 16, k0, lane);
                ldA80(pl[bt], bu + 40960, wn * 32 + bt * 16, k0, lane);
            }
            #pragma unroll
            for (int mt = 0; mt < 4; ++mt)
                #pragma unroll
                for (int n8 = 0; n8 < 4; ++n8) {
                    const int bt = n8 >> 1, sl = n8 & 1;
                    mma16816(aG[mt][n8], ah[mt], gh[bt][sl], gh[bt][2 + sl]);
                    mma16816(aG[mt][n8], al[mt], gh[bt][sl], gh[bt][2 + sl]);
                    mma16816(aP[mt][n8], ah[mt], ph[bt][sl], ph[bt][2 + sl]);
                    mma16816(aP[mt][n8], al[mt], ph[bt][sl], ph[bt][2 + sl]);
                    mma16816(aP[mt][n8], ah[mt], pl[bt][sl], pl[bt][2 + sl]);
                }
        }
        if (s + 1 < 16) {
            #pragma unroll
            for (int i = 0; i < 8; ++i) {
                int e = t + i * 256; int l = e & 127; int cp = e >> 7;
                u16 h0, q0, h1, q1; hsplit(xv0[i], h0, q0); hsplit(xv1[i], h1, q1);
                *(u32*)(nbuf + l * 80 + cp * 4) = (u32)h0 | ((u32)h1 << 16);
                *(u32*)(nbuf + 10240 + l * 80 + cp * 4) = (u32)q0 | ((u32)q1 << 16);
            }
        }
        __syncthreads();
    }

    // epilogue G (descale 1/64, +bias) -> d_gh [l][a] fp16 single
    #pragma unroll
    for (int mt = 0; mt < 4; ++mt)
        #pragma unroll
        for (int n8 = 0; n8 < 4; ++n8) {
            const int l = l0 + wm * 64 + mt * 16 + (lane >> 2);
            const int a = a0 + wn * 32 + n8 * 8 + ((lane & 3) << 1);
            const float b0 = __ldg(bg + a), b1 = __ldg(bg + a + 1);
            const size_t i0 = ((size_t)nb * HWD + l) * AA + a;
            u16 g0 = h1(aG[mt][n8][0] * 0.015625f + b0);
            u16 g1 = h1(aG[mt][n8][1] * 0.015625f + b1);
            u16 g2 = h1(aG[mt][n8][2] * 0.015625f + b0);
            u16 g3 = h1(aG[mt][n8][3] * 0.015625f + b1);
            *(u32*)(d_gh + i0) = (u32)g0 | ((u32)g1 << 16);
            *(u32*)(d_gh + i0 + (size_t)8 * AA) = (u32)g2 | ((u32)g3 << 16);
        }

    // epilogue Phi: transpose to ts[a][132] fp32, then fused 2x2 pool -> d_pp
    float* ts = (float*)sm;
    #pragma unroll
    for (int mt = 0; mt < 4; ++mt)
        #pragma unroll
        for (int n8 = 0; n8 < 4; ++n8) {
            const int nl = wn * 32 + n8 * 8 + ((lane & 3) << 1);
            const int ml = wm * 64 + mt * 16 + (lane >> 2);
            const float b0 = __ldg(bp + a0 + nl), b1 = __ldg(bp + a0 + nl + 1);
            ts[nl * 132 + ml] = aP[mt][n8][0] * 0.015625f + b0;
            ts[(nl + 1) * 132 + ml] = aP[mt][n8][1] * 0.015625f + b1;
            ts[nl * 132 + ml + 8] = aP[mt][n8][2] * 0.015625f + b0;
            ts[(nl + 1) * 132 + ml + 8] = aP[mt][n8][3] * 0.015625f + b1;
        }
    __syncthreads();
    // block covers image rows 2b,2b+1 (b = l0/128) -> pooled row b, 32 cols
    const int pb = l0 >> 7;
    #pragma unroll
    for (int i = 0; i < 16; ++i) {
        int e = t + i * 256; int a = e >> 5; int w = e & 31;
        float v = fmaxf(fmaxf(ts[a * 132 + 2 * w], ts[a * 132 + 2 * w + 1]),
                        fmaxf(ts[a * 132 + 64 + 2 * w], ts[a * 132 + 65 + 2 * w]));
        u16 h, l; hsplit(v, h, l);
        const size_t o = ((size_t)nb * AA + a0 + a) * PHW + pb * 32 + w;
        d_pph[o] = h; d_ppl[o] = l;
    }
}

// ===========================================================================
// cmat + fused softmax: cm[c][a] = theta . phi^T (3-term), row softmax, store
// attn fp16 hi/lo. CTA 128c x 256a full row, 512 threads, K=1024 BK=64.
// buf: Ah 0(16K), Al 16384, Bh 32768(32K), Bl 65536(32K)  (CM_STG=98304)
// ===========================================================================
#define CM_STG 98304
#define CM_SMEM (2 * CM_STG)
__global__ __launch_bounds__(512) void cmat_mma() {
    extern __shared__ char sm[];
    const u32 sb = smem_u32(sm);
    const int t = threadIdx.x, lane = t & 31, wp_ = t >> 5;
    const int wm = wp_ >> 3, wn = wp_ & 7;  // 2 x 8 warps; warp tile 64c x 32a
    const int nb = blockIdx.y, c0 = blockIdx.x * 128;
    const u16* TH = d_thh + ((size_t)nb * CCH + c0) * PHW;
    const u16* TL = d_thl + ((size_t)nb * CCH + c0) * PHW;
    const u16* PH = d_pph + (size_t)nb * AA * PHW;
    const u16* PL = d_ppl + (size_t)nb * AA * PHW;

    float acc[4][4][4] = {};

    // staging helpers inline (512 threads)
    #define STG_A(dst, src) do {                                                   \
        _Pragma("unroll")                                                          \
        for (int i_ = 0; i_ < 2; ++i_) {                                           \
            int idx_ = t + i_ * 512; int r_ = idx_ >> 3, ch_ = idx_ & 7;           \
            cpa((dst) + r_ * 128 + (((ch_ ^ (r_ & 7)) & 7) << 4),                  \
                (src) + (size_t)r_ * PHW + ch_ * 8);                               \
        } } while (0)
    #define STG_B(dst, src) do {                                                   \
        _Pragma("unroll")                                                          \
        for (int i_ = 0; i_ < 4; ++i_) {                                           \
            int idx_ = t + i_ * 512; int r_ = idx_ >> 3, ch_ = idx_ & 7;           \
            cpa((dst) + r_ * 128 + (((ch_ ^ (r_ & 7)) & 7) << 4),                  \
                (src) + (size_t)r_ * PHW + ch_ * 8);                               \
        } } while (0)

    STG_A(sb, TH); STG_A(sb + 16384, TL);
    STG_B(sb + 32768, PH); STG_B(sb + 65536, PL);
    CPC;
    #pragma unroll 1
    for (int s = 0; s < 16; ++s) {
        const int buf = s & 1;
        if (s + 1 < 16) {
            const u32 nbu = sb + (buf ^ 1) * CM_STG;
            const int k0 = (s + 1) * 64;
            STG_A(nbu, TH + k0); STG_A(nbu + 16384, TL + k0);
            STG_B(nbu + 32768, PH + k0); STG_B(nbu + 65536, PL + k0);
            CPC; CP_WAIT1;
        } else { CP_WAIT0; }
        __syncthreads();
        const u32 bu = sb + buf * CM_STG;
        #pragma unroll
        for (int ks = 0; ks < 4; ++ks) {
            const int k0 = ks * 16;
            unsigned ah[4][4], al[4][4], bh[2][4], bl[2][4];
            #pragma unroll
            for (int mt = 0; mt < 4; ++mt) {
                ldA128(ah[mt], bu, wm * 64 + mt * 16, k0, lane);
                ldA128(al[mt], bu + 16384, wm * 64 + mt * 16, k0, lane);
            }
            #pragma unroll
            for (int bt = 0; bt < 2; ++bt) {
                ldA128(bh[bt], bu + 32768, wn * 32 + bt * 16, k0, lane);
                ldA128(bl[bt], bu + 65536, wn * 32 + bt * 16, k0, lane);
            }
            #pragma unroll
            for (int mt = 0; mt < 4; ++mt)
                #pragma unroll
                for (int n8 = 0; n8 < 4; ++n8) {
                    const int bt = n8 >> 1, sl = n8 & 1;
                    mma16816(acc[mt][n8], ah[mt], bh[bt][sl], bh[bt][2 + sl]);
                    mma16816(acc[mt][n8], al[mt], bh[bt][sl], bh[bt][2 + sl]);
                    mma16816(acc[mt][n8], ah[mt], bl[bt][sl], bl[bt][2 + sl]);
                }
        }
        __syncthreads();
    }
    #undef STG_A
    #undef STG_B

    // ---- fused softmax over a=256 (rows c) ----
    float* red = (float*)sm;  // [wm2][mt4][rs2][rl8][wn8] = 1024 floats
    const int rl = lane >> 2, l3 = lane & 3;
    float rmax[4][2], rinv[4][2];

    #pragma unroll
    for (int mt = 0; mt < 4; ++mt)
        #pragma unroll
        for (int rs = 0; rs < 2; ++rs) {
            float m = -3.0e38f;
            #pragma unroll
            for (int n8 = 0; n8 < 4; ++n8) {
                m = fmaxf(m, acc[mt][n8][rs * 2]);
                m = fmaxf(m, acc[mt][n8][rs * 2 + 1]);
            }
            m = fmaxf(m, __shfl_xor_sync(0xffffffffu, m, 1));
            m = fmaxf(m, __shfl_xor_sync(0xffffffffu, m, 2));
            if (l3 == 0) red[(((wm * 4 + mt) * 2 + rs) * 8 + rl) * 8 + wn] = m;
        }
    __syncthreads();
    #pragma unroll
    for (int mt = 0; mt < 4; ++mt)
        #pragma unroll
        for (int rs = 0; rs < 2; ++rs) {
            float m = -3.0e38f;
            #pragma unroll
            for (int w8 = 0; w8 < 8; ++w8)
                m = fmaxf(m, red[(((wm * 4 + mt) * 2 + rs) * 8 + rl) * 8 + w8]);
            rmax[mt][rs] = m;
        }
    __syncthreads();
    #pragma unroll
    for (int mt = 0; mt < 4; ++mt)
        #pragma unroll
        for (int rs = 0; rs < 2; ++rs) {
            float s = 0.f;
            #pragma unroll
            for (int n8 = 0; n8 < 4; ++n8) {
                float e0 = expf(acc[mt][n8][rs * 2] - rmax[mt][rs]);
                float e1 = expf(acc[mt][n8][rs * 2 + 1] - rmax[mt][rs]);
                acc[mt][n8][rs * 2] = e0; acc[mt][n8][rs * 2 + 1] = e1;
                s += e0 + e1;
            }
            s += __shfl_xor_sync(0xffffffffu, s, 1);
            s += __shfl_xor_sync(0xffffffffu, s, 2);
            if (l3 == 0) red[(((wm * 4 + mt) * 2 + rs) * 8 + rl) * 8 + wn] = s;
        }
    __syncthreads();
    #pragma unroll
    for (int mt = 0; mt < 4; ++mt)
        #pragma unroll
        for (int rs = 0; rs < 2; ++rs) {
            float s = 0.f;
            #pragma unroll
            for (int w8 = 0; w8 < 8; ++w8)
                s += red[(((wm * 4 + mt) * 2 + rs) * 8 + rl) * 8 + w8];
            rinv[mt][rs] = 1.0f / s;
        }

    #pragma unroll
    for (int mt = 0; mt < 4; ++mt)
        #pragma unroll
        for (int n8 = 0; n8 < 4; ++n8) {
            const int c = c0 + wm * 64 + mt * 16 + rl;
            const int a = wn * 32 + n8 * 8 + 2 * l3;
            size_t i0 = ((size_t)nb * CCH + c) * AA + a;
            u16 h0, q0, h1, q1;
            hsplit(acc[mt][n8][0] * rinv[mt][0], h0, q0);
            hsplit(acc[mt][n8][1] * rinv[mt][0], h1, q1);
            *(u32*)(d_ath + i0) = (u32)h0 | ((u32)h1 << 16);
            *(u32*)(d_atl + i0) = (u32)q0 | ((u32)q1 << 16);
            i0 += (size_t)8 * AA;
            hsplit(acc[mt][n8][2] * rinv[mt][1], h0, q0);
            hsplit(acc[mt][n8][3] * rinv[mt][1], h1, q1);
            *(u32*)(d_ath + i0) = (u32)h0 | ((u32)h1 << 16);
            *(u32*)(d_atl + i0) = (u32)q0 | ((u32)q1 << 16);
        }
}

// ===========================================================================
// final: out[c][l] = (attn_hi + attn_lo) . G_hi + x  (2-term), K=256, BK=64
// buf: AH 0(16K), AL 16384, BH 32768(16K)  (FN_STG=49152)
// ===========================================================================
#define FN_STG 49152
#define FN_SMEM (2 * FN_STG)
__global__ __launch_bounds__(256) void final_mma(const float* __restrict__ x,
                                                 float* __restrict__ out) {
    extern __shared__ char sm[];
    const u32 sb = smem_u32(sm);
    const int t = threadIdx.x, lane = t & 31;
    const int wm = (t >> 5) & 1, wn = t >> 6;
    const int nb = blockIdx.z, c0 = blockIdx.y * 128, l0 = blockIdx.x * 128;
    const u16* AH = d_ath + ((size_t)nb * CCH + c0) * AA;
    const u16* AL = d_atl + ((size_t)nb * CCH + c0) * AA;
    const u16* BH = d_gh + ((size_t)nb * HWD + l0) * AA;

    float acc[4][4][4] = {};

    #define STG(dst, src, ld) do {                                                 \
        _Pragma("unroll")                                                          \
        for (int i_ = 0; i_ < 4; ++i_) {                                           \
            int idx_ = t + i_ * 256; int r_ = idx_ >> 3, ch_ = idx_ & 7;           \
            cpa((dst) + r_ * 128 + (((ch_ ^ (r_ & 7)) & 7) << 4),                  \
                (src) + (size_t)r_ * (ld) + ch_ * 8);                              \
        } } while (0)

    STG(sb, AH, AA); STG(sb + 16384, AL, AA); STG(sb + 32768, BH, AA);
    CPC;
    #pragma unroll 1
    for (int s = 0; s < 4; ++s) {
        const int buf = s & 1;
        if (s + 1 < 4) {
            const u32 nbu = sb + (buf ^ 1) * FN_STG;
            const int k0 = (s + 1) * 64;
            STG(nbu, AH + k0, AA); STG(nbu + 16384, AL + k0, AA);
            STG(nbu + 32768, BH + k0, AA);
            CPC; CP_WAIT1;
        } else { CP_WAIT0; }
        __syncthreads();
        const u32 bu = sb + buf * FN_STG;
        #pragma unroll
        for (int ks = 0; ks < 4; ++ks) {
            const int k0 = ks * 16;
            unsigned ah[4][4], al[4][4], bh[2][4];
            #pragma unroll
            for (int mt = 0; mt < 4; ++mt) {
                ldA128(ah[mt], bu, wm * 64 + mt * 16, k0, lane);
                ldA128(al[mt], bu + 16384, wm * 64 + mt * 16, k0, lane);
            }
            #pragma unroll
            for (int bt = 0; bt < 2; ++bt)
                ldA128(bh[bt], bu + 32768, wn * 32 + bt * 16, k0, lane);
            #pragma unroll
            for (int mt = 0; mt < 4; ++mt)
                #pragma unroll
                for (int n8 = 0; n8 < 4; ++n8) {
                    const int bt = n8 >> 1, sl = n8 & 1;
                    mma16816(acc[mt][n8], ah[mt], bh[bt][sl], bh[bt][2 + sl]);
                    mma16816(acc[mt][n8], al[mt], bh[bt][sl], bh[bt][2 + sl]);
                }
        }
        __syncthreads();
    }
    #undef STG

    #pragma unroll
    for (int mt = 0; mt < 4; ++mt)
        #pragma unroll
        for (int n8 = 0; n8 < 4; ++n8) {
            const int c = c0 + wm * 64 + mt * 16 + (lane >> 2);
            const int l = l0 + wn * 32 + n8 * 8 + ((lane & 3) << 1);
            size_t i0 = ((size_t)nb * CCH + c) * HWD + l;
            float2 xv = *(const float2*)(x + i0);
            float2 o0; o0.x = acc[mt][n8][0] + xv.x; o0.y = acc[mt][n8][1] + xv.y;
            *(float2*)(out + i0) = o0;
            i0 += (size_t)8 * HWD;
            float2 xw = *(const float2*)(x + i0);
            float2 o1; o1.x = acc[mt][n8][2] + xw.x; o1.y = acc[mt][n8][3] + xw.y;
            *(float2*)(out + i0) = o1;
        }
}

// ===========================================================================
extern "C" void kernel_launch(void* const* d_in, const int* in_sizes, int n_in,
                              void* d_out, int out_size) {
    (void)in_sizes; (void)n_in; (void)out_size;
    const float* x  = (const float*)d_in[0];
    const float* wg = (const float*)d_in[1];
    const float* bg = (const float*)d_in[2];
    const float* wp = (const float*)d_in[3];
    const float* bp = (const float*)d_in[4];
    float* out = (float*)d_out;

    cudaFuncSetAttribute(conv_mma,  cudaFuncAttributeMaxDynamicSharedMemorySize, CV_SMEM);
    cudaFuncSetAttribute(cmat_mma,  cudaFuncAttributeMaxDynamicSharedMemorySize, CM_SMEM);
    cudaFuncSetAttribute(final_mma, cudaFuncAttributeMaxDynamicSharedMemorySize, FN_SMEM);

    split_w_k<<<1024, 256>>>(wg, wp);
    pool_theta_k<<<65536, 256>>>(x);

    conv_mma<<<dim3(32, 2, NB), 256, CV_SMEM>>>(x, bg, bp);

    cmat_mma<<<dim3(4, NB), 512, CM_SMEM>>>();

    final_mma<<<dim3(32, 4, NB), 256, FN_SMEM>>>(x, out);
}

// round 7
// speedup vs baseline: 3.5028x; 1.1779x over previous
#include <cuda_runtime.h>
#include <cuda_fp16.h>
#include <cstdint>

#define NB 32
#define CCH 512
#define AA 256
#define HWD 4096
#define PHW 1024

typedef unsigned int u32;
typedef unsigned short u16;

// ---------------- scratch (static device globals) ---------------------------
__device__ __align__(16) u16 d_wh[262144], d_wl[262144];       // [512][512] rows 0-255 Wg, 256-511 Wphi (x64 scaled)
__device__ __align__(16) u16 d_gh[33554432];                   // [n][l][a] fp16 single
__device__ __align__(16) u16 d_thh[16777216], d_thl[16777216]; // [n][c][m]
__device__ __align__(16) u16 d_pph[8388608], d_ppl[8388608];   // [n][a][m]
__device__ __align__(16) u16 d_ath[4194304];                   // [n][c][a] fp16 single

// ---------------- helpers ---------------------------------------------------
__device__ __forceinline__ u32 smem_u32(const void* p) {
    u32 a;
    asm("{ .reg .u64 t; cvta.to.shared.u64 t, %1; cvt.u32.u64 %0, t; }" : "=r"(a) : "l"(p));
    return a;
}
__device__ __forceinline__ void cpa(u32 d, const void* s) {
    asm volatile("cp.async.cg.shared.global [%0],[%1],16;" :: "r"(d), "l"(s));
}
#define CPC      asm volatile("cp.async.commit_group;" ::: "memory")
#define CP_WAIT1 asm volatile("cp.async.wait_group 1;" ::: "memory")
#define CP_WAIT0 asm volatile("cp.async.wait_group 0;" ::: "memory")

__device__ __forceinline__ void ldsm4(unsigned f[4], u32 a) {
    asm volatile("ldmatrix.sync.aligned.m8n8.x4.shared.b16 {%0,%1,%2,%3},[%4];"
                 : "=r"(f[0]), "=r"(f[1]), "=r"(f[2]), "=r"(f[3]) : "r"(a));
}
__device__ __forceinline__ void mma16816(float c[4], const unsigned a[4], unsigned b0, unsigned b1) {
    asm volatile("mma.sync.aligned.m16n8k16.row.col.f32.f16.f16.f32 "
                 "{%0,%1,%2,%3},{%4,%5,%6,%7},{%8,%9},{%0,%1,%2,%3};"
                 : "+f"(c[0]), "+f"(c[1]), "+f"(c[2]), "+f"(c[3])
                 : "r"(a[0]), "r"(a[1]), "r"(a[2]), "r"(a[3]), "r"(b0), "r"(b1));
}
__device__ __forceinline__ void hsplit(float v, u16& h, u16& l) {
    __half hh = __float2half_rn(v);
    h = __half_as_ushort(hh);
    l = __half_as_ushort(__float2half_rn(v - __half2float(hh)));
}
__device__ __forceinline__ u16 h1(float v) { return __half_as_ushort(__float2half_rn(v)); }

// ldmatrix fragment from 128B-pitch SW128-swizzled K-major tile
__device__ __forceinline__ void ldA128(unsigned f[4], u32 tb, int r0, int k0, int lane) {
    int row = r0 + (lane & 15);
    int ch = (k0 >> 3) + (lane >> 4);
    ldsm4(f, tb + row * 128 + (((ch ^ (row & 7)) & 7) << 4));
}
// ldmatrix fragment from 80B-pitch (32-k) tile, no swizzle
__device__ __forceinline__ void ldA80(unsigned f[4], u32 tb, int r0, int k0, int lane) {
    int row = r0 + (lane & 15);
    int ch = (k0 >> 3) + (lane >> 4);
    ldsm4(f, tb + row * 80 + (ch << 4));
}
// cp.async stage of 128row x 32k fp16 tile (80B pitch), ld=512 (for W)
__device__ __forceinline__ void stage80(u32 dst, const u16* src, int t) {
    #pragma unroll
    for (int i = 0; i < 2; ++i) {
        int idx = t + i * 256;
        int row = idx >> 2, ch = idx & 3;
        cpa(dst + row * 80 + (ch << 4), src + (size_t)row * 512 + ch * 8);
    }
}

// ===========================================================================
// split_w: (Wg,Wphi)*64 -> fp16 hi/lo  [512][512]
// ===========================================================================
__global__ __launch_bounds__(256) void split_w_k(const float* __restrict__ wg,
                                                 const float* __restrict__ wp) {
    int idx = blockIdx.x * 256 + threadIdx.x;
    int r = idx >> 9, c = idx & 511;
    float v = ((r < 256) ? wg[r * 512 + c] : wp[(r - 256) * 512 + c]) * 64.0f;
    u16 h, l; hsplit(v, h, l);
    d_wh[idx] = h; d_wl[idx] = l;
}

// ===========================================================================
// pool_theta: 2x2 max of x -> fp16 hi/lo
// ===========================================================================
__global__ __launch_bounds__(256) void pool_theta_k(const float* __restrict__ x) {
    const size_t idx = (size_t)blockIdx.x * 256 + threadIdx.x;
    const int m = (int)(idx & 1023);
    const size_t nc = idx >> 10;
    const int r = m >> 5, w = m & 31;
    const float* p = x + nc * HWD + (size_t)(2 * r) * 64 + 2 * w;
    float v = fmaxf(fmaxf(p[0], p[1]), fmaxf(p[64], p[65]));
    u16 h, l; hsplit(v, h, l);
    d_thh[idx] = h; d_thl[idx] = l;
}

// ===========================================================================
// conv: G[l][a] fp16 (1-term), phi pooled fp16 hi/lo (3-term + fused 2x2 pool)
// M=l 128, N=a 128, K=c 512, BK=32, 2-stage.
// buf: Xh 0, Xl 10240, Gh 20480, Ph 30720, Pl 40960   (CV_STG=51200)
// ===========================================================================
#define CV_STG 51200
#define CV_SMEM (2 * CV_STG)
__global__ __launch_bounds__(256) void conv_mma(const float* __restrict__ x,
                                                const float* __restrict__ bg,
                                                const float* __restrict__ bp) {
    extern __shared__ char sm[];
    const u32 sb = smem_u32(sm);
    const int t = threadIdx.x, lane = t & 31;
    const int wm = (t >> 5) & 1, wn = t >> 6;
    const int nb = blockIdx.z, a0 = blockIdx.y * 128, l0 = blockIdx.x * 128;
    const float* X = x + (size_t)nb * CCH * HWD;

    float aG[4][4][4] = {};
    float aP[4][4][4] = {};
    float xv0[8], xv1[8];

    {
        #pragma unroll
        for (int i = 0; i < 8; ++i) {
            int e = t + i * 256; int l = e & 127; int cp = e >> 7;
            xv0[i] = X[(size_t)(2 * cp) * HWD + l0 + l];
            xv1[i] = X[(size_t)(2 * cp + 1) * HWD + l0 + l];
        }
        stage80(sb + 20480, d_wh + (size_t)a0 * 512, t);
        stage80(sb + 30720, d_wh + (size_t)(256 + a0) * 512, t);
        stage80(sb + 40960, d_wl + (size_t)(256 + a0) * 512, t);
        CPC;
        #pragma unroll
        for (int i = 0; i < 8; ++i) {
            int e = t + i * 256; int l = e & 127; int cp = e >> 7;
            u16 h0, q0, h1c, q1; hsplit(xv0[i], h0, q0); hsplit(xv1[i], h1c, q1);
            *(u32*)(sm + l * 80 + cp * 4) = (u32)h0 | ((u32)h1c << 16);
            *(u32*)(sm + 10240 + l * 80 + cp * 4) = (u32)q0 | ((u32)q1 << 16);
        }
    }

    #pragma unroll 1
    for (int s = 0; s < 16; ++s) {
        const int buf = s & 1;
        char* nbuf = sm + (buf ^ 1) * CV_STG;
        const u32 nbu = sb + (buf ^ 1) * CV_STG;
        if (s + 1 < 16) {
            const int k0 = (s + 1) * 32;
            #pragma unroll
            for (int i = 0; i < 8; ++i) {
                int e = t + i * 256; int l = e & 127; int cp = e >> 7;
                xv0[i] = X[(size_t)(k0 + 2 * cp) * HWD + l0 + l];
                xv1[i] = X[(size_t)(k0 + 2 * cp + 1) * HWD + l0 + l];
            }
            stage80(nbu + 20480, d_wh + (size_t)a0 * 512 + k0, t);
            stage80(nbu + 30720, d_wh + (size_t)(256 + a0) * 512 + k0, t);
            stage80(nbu + 40960, d_wl + (size_t)(256 + a0) * 512 + k0, t);
            CPC; CP_WAIT1;
        } else { CP_WAIT0; }
        __syncthreads();

        const u32 bu = sb + buf * CV_STG;
        #pragma unroll
        for (int ks = 0; ks < 2; ++ks) {
            const int k0 = ks * 16;
            unsigned ah[4][4], al[4][4];
            #pragma unroll
            for (int mt = 0; mt < 4; ++mt) {
                ldA80(ah[mt], bu, wm * 64 + mt * 16, k0, lane);
                ldA80(al[mt], bu + 10240, wm * 64 + mt * 16, k0, lane);
            }
            unsigned gh[2][4], ph[2][4], pl[2][4];
            #pragma unroll
            for (int bt = 0; bt < 2; ++bt) {
                ldA80(gh[bt], bu + 20480, wn * 32 + bt * 16, k0, lane);
                ldA80(ph[bt], bu + 30720, wn * 32 + bt * 16, k0, lane);
                ldA80(pl[bt], bu + 40960, wn * 32 + bt * 16, k0, lane);
            }
            #pragma unroll
            for (int mt = 0; mt < 4; ++mt)
                #pragma unroll
                for (int n8 = 0; n8 < 4; ++n8) {
                    const int bt = n8 >> 1, sl = n8 & 1;
                    mma16816(aG[mt][n8], ah[mt], gh[bt][sl], gh[bt][2 + sl]);
                    mma16816(aP[mt][n8], ah[mt], ph[bt][sl], ph[bt][2 + sl]);
                    mma16816(aP[mt][n8], al[mt], ph[bt][sl], ph[bt][2 + sl]);
                    mma16816(aP[mt][n8], ah[mt], pl[bt][sl], pl[bt][2 + sl]);
                }
        }
        if (s + 1 < 16) {
            #pragma unroll
            for (int i = 0; i < 8; ++i) {
                int e = t + i * 256; int l = e & 127; int cp = e >> 7;
                u16 h0, q0, h1c, q1; hsplit(xv0[i], h0, q0); hsplit(xv1[i], h1c, q1);
                *(u32*)(nbuf + l * 80 + cp * 4) = (u32)h0 | ((u32)h1c << 16);
                *(u32*)(nbuf + 10240 + l * 80 + cp * 4) = (u32)q0 | ((u32)q1 << 16);
            }
        }
        __syncthreads();
    }

    // epilogue G (descale 1/64, +bias) -> d_gh [l][a] fp16 single
    #pragma unroll
    for (int mt = 0; mt < 4; ++mt)
        #pragma unroll
        for (int n8 = 0; n8 < 4; ++n8) {
            const int l = l0 + wm * 64 + mt * 16 + (lane >> 2);
            const int a = a0 + wn * 32 + n8 * 8 + ((lane & 3) << 1);
            const float b0 = __ldg(bg + a), b1 = __ldg(bg + a + 1);
            const size_t i0 = ((size_t)nb * HWD + l) * AA + a;
            u16 g0 = h1(aG[mt][n8][0] * 0.015625f + b0);
            u16 g1 = h1(aG[mt][n8][1] * 0.015625f + b1);
            u16 g2 = h1(aG[mt][n8][2] * 0.015625f + b0);
            u16 g3 = h1(aG[mt][n8][3] * 0.015625f + b1);
            *(u32*)(d_gh + i0) = (u32)g0 | ((u32)g1 << 16);
            *(u32*)(d_gh + i0 + (size_t)8 * AA) = (u32)g2 | ((u32)g3 << 16);
        }

    // epilogue Phi: transpose to ts[a][132] fp32, then fused 2x2 pool -> d_pp
    float* ts = (float*)sm;
    #pragma unroll
    for (int mt = 0; mt < 4; ++mt)
        #pragma unroll
        for (int n8 = 0; n8 < 4; ++n8) {
            const int nl = wn * 32 + n8 * 8 + ((lane & 3) << 1);
            const int ml = wm * 64 + mt * 16 + (lane >> 2);
            const float b0 = __ldg(bp + a0 + nl), b1 = __ldg(bp + a0 + nl + 1);
            ts[nl * 132 + ml] = aP[mt][n8][0] * 0.015625f + b0;
            ts[(nl + 1) * 132 + ml] = aP[mt][n8][1] * 0.015625f + b1;
            ts[nl * 132 + ml + 8] = aP[mt][n8][2] * 0.015625f + b0;
            ts[(nl + 1) * 132 + ml + 8] = aP[mt][n8][3] * 0.015625f + b1;
        }
    __syncthreads();
    const int pb = l0 >> 7;
    #pragma unroll
    for (int i = 0; i < 16; ++i) {
        int e = t + i * 256; int a = e >> 5; int w = e & 31;
        float v = fmaxf(fmaxf(ts[a * 132 + 2 * w], ts[a * 132 + 2 * w + 1]),
                        fmaxf(ts[a * 132 + 64 + 2 * w], ts[a * 132 + 65 + 2 * w]));
        u16 h, l; hsplit(v, h, l);
        const size_t o = ((size_t)nb * AA + a0 + a) * PHW + pb * 32 + w;
        d_pph[o] = h; d_ppl[o] = l;
    }
}

// ===========================================================================
// cmat + fused softmax: theta . phi^T (3-term), row softmax, attn fp16 single.
// CTA 128c x 256a full row, 512 threads, K=1024 BK=64.
// buf: Ah 0(16K), Al 16384, Bh 32768(32K), Bl 65536(32K)  (CM_STG=98304)
// ===========================================================================
#define CM_STG 98304
#define CM_SMEM (2 * CM_STG)
__global__ __launch_bounds__(512) void cmat_mma() {
    extern __shared__ char sm[];
    const u32 sb = smem_u32(sm);
    const int t = threadIdx.x, lane = t & 31, wp_ = t >> 5;
    const int wm = wp_ >> 3, wn = wp_ & 7;
    const int nb = blockIdx.y, c0 = blockIdx.x * 128;
    const u16* TH = d_thh + ((size_t)nb * CCH + c0) * PHW;
    const u16* TL = d_thl + ((size_t)nb * CCH + c0) * PHW;
    const u16* PH = d_pph + (size_t)nb * AA * PHW;
    const u16* PL = d_ppl + (size_t)nb * AA * PHW;

    float acc[4][4][4] = {};

    #define STG_A(dst, src) do {                                                   \
        _Pragma("unroll")                                                          \
        for (int i_ = 0; i_ < 2; ++i_) {                                           \
            int idx_ = t + i_ * 512; int r_ = idx_ >> 3, ch_ = idx_ & 7;           \
            cpa((dst) + r_ * 128 + (((ch_ ^ (r_ & 7)) & 7) << 4),                  \
                (src) + (size_t)r_ * PHW + ch_ * 8);                               \
        } } while (0)
    #define STG_B(dst, src) do {                                                   \
        _Pragma("unroll")                                                          \
        for (int i_ = 0; i_ < 4; ++i_) {                                           \
            int idx_ = t + i_ * 512; int r_ = idx_ >> 3, ch_ = idx_ & 7;           \
            cpa((dst) + r_ * 128 + (((ch_ ^ (r_ & 7)) & 7) << 4),                  \
                (src) + (size_t)r_ * PHW + ch_ * 8);                               \
        } } while (0)

    STG_A(sb, TH); STG_A(sb + 16384, TL);
    STG_B(sb + 32768, PH); STG_B(sb + 65536, PL);
    CPC;
    #pragma unroll 1
    for (int s = 0; s < 16; ++s) {
        const int buf = s & 1;
        if (s + 1 < 16) {
            const u32 nbu = sb + (buf ^ 1) * CM_STG;
            const int k0 = (s + 1) * 64;
            STG_A(nbu, TH + k0); STG_A(nbu + 16384, TL + k0);
            STG_B(nbu + 32768, PH + k0); STG_B(nbu + 65536, PL + k0);
            CPC; CP_WAIT1;
        } else { CP_WAIT0; }
        __syncthreads();
        const u32 bu = sb + buf * CM_STG;
        #pragma unroll
        for (int ks = 0; ks < 4; ++ks) {
            const int k0 = ks * 16;
            unsigned ah[4][4], al[4][4], bh[2][4], bl[2][4];
            #pragma unroll
            for (int mt = 0; mt < 4; ++mt) {
                ldA128(ah[mt], bu, wm * 64 + mt * 16, k0, lane);
                ldA128(al[mt], bu + 16384, wm * 64 + mt * 16, k0, lane);
            }
            #pragma unroll
            for (int bt = 0; bt < 2; ++bt) {
                ldA128(bh[bt], bu + 32768, wn * 32 + bt * 16, k0, lane);
                ldA128(bl[bt], bu + 65536, wn * 32 + bt * 16, k0, lane);
            }
            #pragma unroll
            for (int mt = 0; mt < 4; ++mt)
                #pragma unroll
                for (int n8 = 0; n8 < 4; ++n8) {
                    const int bt = n8 >> 1, sl = n8 & 1;
                    mma16816(acc[mt][n8], ah[mt], bh[bt][sl], bh[bt][2 + sl]);
                    mma16816(acc[mt][n8], al[mt], bh[bt][sl], bh[bt][2 + sl]);
                    mma16816(acc[mt][n8], ah[mt], bl[bt][sl], bl[bt][2 + sl]);
                }
        }
        __syncthreads();
    }
    #undef STG_A
    #undef STG_B

    // ---- fused softmax over a=256 ----
    float* red = (float*)sm;
    const int rl = lane >> 2, l3 = lane & 3;
    float rmax[4][2], rinv[4][2];

    #pragma unroll
    for (int mt = 0; mt < 4; ++mt)
        #pragma unroll
        for (int rs = 0; rs < 2; ++rs) {
            float m = -3.0e38f;
            #pragma unroll
            for (int n8 = 0; n8 < 4; ++n8) {
                m = fmaxf(m, acc[mt][n8][rs * 2]);
                m = fmaxf(m, acc[mt][n8][rs * 2 + 1]);
            }
            m = fmaxf(m, __shfl_xor_sync(0xffffffffu, m, 1));
            m = fmaxf(m, __shfl_xor_sync(0xffffffffu, m, 2));
            if (l3 == 0) red[(((wm * 4 + mt) * 2 + rs) * 8 + rl) * 8 + wn] = m;
        }
    __syncthreads();
    #pragma unroll
    for (int mt = 0; mt < 4; ++mt)
        #pragma unroll
        for (int rs = 0; rs < 2; ++rs) {
            float m = -3.0e38f;
            #pragma unroll
            for (int w8 = 0; w8 < 8; ++w8)
                m = fmaxf(m, red[(((wm * 4 + mt) * 2 + rs) * 8 + rl) * 8 + w8]);
            rmax[mt][rs] = m;
        }
    __syncthreads();
    #pragma unroll
    for (int mt = 0; mt < 4; ++mt)
        #pragma unroll
        for (int rs = 0; rs < 2; ++rs) {
            float s = 0.f;
            #pragma unroll
            for (int n8 = 0; n8 < 4; ++n8) {
                float e0 = expf(acc[mt][n8][rs * 2] - rmax[mt][rs]);
                float e1 = expf(acc[mt][n8][rs * 2 + 1] - rmax[mt][rs]);
                acc[mt][n8][rs * 2] = e0; acc[mt][n8][rs * 2 + 1] = e1;
                s += e0 + e1;
            }
            s += __shfl_xor_sync(0xffffffffu, s, 1);
            s += __shfl_xor_sync(0xffffffffu, s, 2);
            if (l3 == 0) red[(((wm * 4 + mt) * 2 + rs) * 8 + rl) * 8 + wn] = s;
        }
    __syncthreads();
    #pragma unroll
    for (int mt = 0; mt < 4; ++mt)
        #pragma unroll
        for (int rs = 0; rs < 2; ++rs) {
            float s = 0.f;
            #pragma unroll
            for (int w8 = 0; w8 < 8; ++w8)
                s += red[(((wm * 4 + mt) * 2 + rs) * 8 + rl) * 8 + w8];
            rinv[mt][rs] = 1.0f / s;
        }

    #pragma unroll
    for (int mt = 0; mt < 4; ++mt)
        #pragma unroll
        for (int n8 = 0; n8 < 4; ++n8) {
            const int c = c0 + wm * 64 + mt * 16 + rl;
            const int a = wn * 32 + n8 * 8 + 2 * l3;
            size_t i0 = ((size_t)nb * CCH + c) * AA + a;
            u16 h0 = h1(acc[mt][n8][0] * rinv[mt][0]);
            u16 hh1 = h1(acc[mt][n8][1] * rinv[mt][0]);
            *(u32*)(d_ath + i0) = (u32)h0 | ((u32)hh1 << 16);
            i0 += (size_t)8 * AA;
            u16 h2 = h1(acc[mt][n8][2] * rinv[mt][1]);
            u16 h3 = h1(acc[mt][n8][3] * rinv[mt][1]);
            *(u32*)(d_ath + i0) = (u32)h2 | ((u32)h3 << 16);
        }
}

// ===========================================================================
// final: out[c][l] = attn_hi . G_hi + x  (1-term), K=256, BK=64
// buf: AH 0(16K), BH 16384(16K)  (FN_STG=32768)
// ===========================================================================
#define FN_STG 32768
#define FN_SMEM (2 * FN_STG)
__global__ __launch_bounds__(256) void final_mma(const float* __restrict__ x,
                                                 float* __restrict__ out) {
    extern __shared__ char sm[];
    const u32 sb = smem_u32(sm);
    const int t = threadIdx.x, lane = t & 31;
    const int wm = (t >> 5) & 1, wn = t >> 6;
    const int nb = blockIdx.z, c0 = blockIdx.y * 128, l0 = blockIdx.x * 128;
    const u16* AH = d_ath + ((size_t)nb * CCH + c0) * AA;
    const u16* BH = d_gh + ((size_t)nb * HWD + l0) * AA;

    float acc[4][4][4] = {};

    #define STG(dst, src, ld) do {                                                 \
        _Pragma("unroll")                                                          \
        for (int i_ = 0; i_ < 4; ++i_) {                                           \
            int idx_ = t + i_ * 256; int r_ = idx_ >> 3, ch_ = idx_ & 7;           \
            cpa((dst) + r_ * 128 + (((ch_ ^ (r_ & 7)) & 7) << 4),                  \
                (src) + (size_t)r_ * (ld) + ch_ * 8);                              \
        } } while (0)

    STG(sb, AH, AA); STG(sb + 16384, BH, AA);
    CPC;
    #pragma unroll 1
    for (int s = 0; s < 4; ++s) {
        const int buf = s & 1;
        if (s + 1 < 4) {
            const u32 nbu = sb + (buf ^ 1) * FN_STG;
            const int k0 = (s + 1) * 64;
            STG(nbu, AH + k0, AA); STG(nbu + 16384, BH + k0, AA);
            CPC; CP_WAIT1;
        } else { CP_WAIT0; }
        __syncthreads();
        const u32 bu = sb + buf * FN_STG;
        #pragma unroll
        for (int ks = 0; ks < 4; ++ks) {
            const int k0 = ks * 16;
            unsigned ah[4][4], bh[2][4];
            #pragma unroll
            for (int mt = 0; mt < 4; ++mt)
                ldA128(ah[mt], bu, wm * 64 + mt * 16, k0, lane);
            #pragma unroll
            for (int bt = 0; bt < 2; ++bt)
                ldA128(bh[bt], bu + 16384, wn * 32 + bt * 16, k0, lane);
            #pragma unroll
            for (int mt = 0; mt < 4; ++mt)
                #pragma unroll
                for (int n8 = 0; n8 < 4; ++n8) {
                    const int bt = n8 >> 1, sl = n8 & 1;
                    mma16816(acc[mt][n8], ah[mt], bh[bt][sl], bh[bt][2 + sl]);
                }
        }
        __syncthreads();
    }
    #undef STG

    #pragma unroll
    for (int mt = 0; mt < 4; ++mt)
        #pragma unroll
        for (int n8 = 0; n8 < 4; ++n8) {
            const int c = c0 + wm * 64 + mt * 16 + (lane >> 2);
            const int l = l0 + wn * 32 + n8 * 8 + ((lane & 3) << 1);
            size_t i0 = ((size_t)nb * CCH + c) * HWD + l;
            float2 xv = *(const float2*)(x + i0);
            float2 o0; o0.x = acc[mt][n8][0] + xv.x; o0.y = acc[mt][n8][1] + xv.y;
            *(float2*)(out + i0) = o0;
            i0 += (size_t)8 * HWD;
            float2 xw = *(const float2*)(x + i0);
            float2 o1; o1.x = acc[mt][n8][2] + xw.x; o1.y = acc[mt][n8][3] + xw.y;
            *(float2*)(out + i0) = o1;
        }
}

// ===========================================================================
extern "C" void kernel_launch(void* const* d_in, const int* in_sizes, int n_in,
                              void* d_out, int out_size) {
    (void)in_sizes; (void)n_in; (void)out_size;
    const float* x  = (const float*)d_in[0];
    const float* wg = (const float*)d_in[1];
    const float* bg = (const float*)d_in[2];
    const float* wp = (const float*)d_in[3];
    const float* bp = (const float*)d_in[4];
    float* out = (float*)d_out;

    cudaFuncSetAttribute(conv_mma,  cudaFuncAttributeMaxDynamicSharedMemorySize, CV_SMEM);
    cudaFuncSetAttribute(cmat_mma,  cudaFuncAttributeMaxDynamicSharedMemorySize, CM_SMEM);
    cudaFuncSetAttribute(final_mma, cudaFuncAttributeMaxDynamicSharedMemorySize, FN_SMEM);

    split_w_k<<<1024, 256>>>(wg, wp);
    pool_theta_k<<<65536, 256>>>(x);

    conv_mma<<<dim3(32, 2, NB), 256, CV_SMEM>>>(x, bg, bp);

    cmat_mma<<<dim3(4, NB), 512, CM_SMEM>>>();

    final_mma<<<dim3(32, 4, NB), 256, FN_SMEM>>>(x, out);
}

// round 8
// speedup vs baseline: 3.5474x; 1.0127x over previous
#include <cuda_runtime.h>
#include <cuda_fp16.h>
#include <cstdint>

#define NB 32
#define CCH 512
#define AA 256
#define HWD 4096
#define PHW 1024

typedef unsigned int u32;
typedef unsigned short u16;

// ---------------- scratch (static device globals) ---------------------------
__device__ __align__(16) u16 d_wh[262144], d_wl[262144];       // [512][512] rows 0-255 Wg, 256-511 Wphi (x64 scaled)
__device__ __align__(16) u16 d_gh[33554432];                   // [n][l][a] fp16 single
__device__ __align__(16) u16 d_thh[16777216], d_thl[16777216]; // [n][c][m]
__device__ __align__(16) u16 d_pph[8388608], d_ppl[8388608];   // [n][a][m]
__device__ __align__(16) u16 d_ath[4194304];                   // [n][c][a] fp16 single

// ---------------- helpers ---------------------------------------------------
__device__ __forceinline__ u32 smem_u32(const void* p) {
    u32 a;
    asm("{ .reg .u64 t; cvta.to.shared.u64 t, %1; cvt.u32.u64 %0, t; }" : "=r"(a) : "l"(p));
    return a;
}
__device__ __forceinline__ void cpa(u32 d, const void* s) {
    asm volatile("cp.async.cg.shared.global [%0],[%1],16;" :: "r"(d), "l"(s));
}
#define CPC      asm volatile("cp.async.commit_group;" ::: "memory")
#define CP_WAIT1 asm volatile("cp.async.wait_group 1;" ::: "memory")
#define CP_WAIT0 asm volatile("cp.async.wait_group 0;" ::: "memory")

__device__ __forceinline__ void ldsm4(unsigned f[4], u32 a) {
    asm volatile("ldmatrix.sync.aligned.m8n8.x4.shared.b16 {%0,%1,%2,%3},[%4];"
                 : "=r"(f[0]), "=r"(f[1]), "=r"(f[2]), "=r"(f[3]) : "r"(a));
}
__device__ __forceinline__ void mma16816(float c[4], const unsigned a[4], unsigned b0, unsigned b1) {
    asm volatile("mma.sync.aligned.m16n8k16.row.col.f32.f16.f16.f32 "
                 "{%0,%1,%2,%3},{%4,%5,%6,%7},{%8,%9},{%0,%1,%2,%3};"
                 : "+f"(c[0]), "+f"(c[1]), "+f"(c[2]), "+f"(c[3])
                 : "r"(a[0]), "r"(a[1]), "r"(a[2]), "r"(a[3]), "r"(b0), "r"(b1));
}
__device__ __forceinline__ void hsplit(float v, u16& h, u16& l) {
    __half hh = __float2half_rn(v);
    h = __half_as_ushort(hh);
    l = __half_as_ushort(__float2half_rn(v - __half2float(hh)));
}
__device__ __forceinline__ u16 h1(float v) { return __half_as_ushort(__float2half_rn(v)); }

// ldmatrix fragment from 128B-pitch SW128-swizzled K-major tile
__device__ __forceinline__ void ldA128(unsigned f[4], u32 tb, int r0, int k0, int lane) {
    int row = r0 + (lane & 15);
    int ch = (k0 >> 3) + (lane >> 4);
    ldsm4(f, tb + row * 128 + (((ch ^ (row & 7)) & 7) << 4));
}
// ldmatrix fragment from 80B-pitch (32-k) tile, no swizzle
__device__ __forceinline__ void ldA80(unsigned f[4], u32 tb, int r0, int k0, int lane) {
    int row = r0 + (lane & 15);
    int ch = (k0 >> 3) + (lane >> 4);
    ldsm4(f, tb + row * 80 + (ch << 4));
}
// cp.async stage of 128row x 32k fp16 tile (80B pitch), ld=512, 512 threads
__device__ __forceinline__ void stage80_512(u32 dst, const u16* src, int t) {
    int row = t >> 2, ch = t & 3;
    cpa(dst + row * 80 + (ch << 4), src + (size_t)row * 512 + ch * 8);
}

// ===========================================================================
// split_w: (Wg,Wphi)*64 -> fp16 hi/lo  [512][512]
// ===========================================================================
__global__ __launch_bounds__(256) void split_w_k(const float* __restrict__ wg,
                                                 const float* __restrict__ wp) {
    int idx = blockIdx.x * 256 + threadIdx.x;
    int r = idx >> 9, c = idx & 511;
    float v = ((r < 256) ? wg[r * 512 + c] : wp[(r - 256) * 512 + c]) * 64.0f;
    u16 h, l; hsplit(v, h, l);
    d_wh[idx] = h; d_wl[idx] = l;
}

// ===========================================================================
// pool_theta: 2x2 max of x -> fp16 hi/lo
// ===========================================================================
__global__ __launch_bounds__(256) void pool_theta_k(const float* __restrict__ x) {
    const size_t idx = (size_t)blockIdx.x * 256 + threadIdx.x;
    const int m = (int)(idx & 1023);
    const size_t nc = idx >> 10;
    const int r = m >> 5, w = m & 31;
    const float* p = x + nc * HWD + (size_t)(2 * r) * 64 + 2 * w;
    float v = fmaxf(fmaxf(p[0], p[1]), fmaxf(p[64], p[65]));
    u16 h, l; hsplit(v, h, l);
    d_thh[idx] = h; d_thl[idx] = l;
}

// ===========================================================================
// conv: G[l][a] fp16 (1-term), phi pooled fp16 hi/lo (3-term + fused 2x2 pool)
// CTA 128l x 128a, 512 threads (16 warps, 2m x 8n, warp 64x16), K=512 BK=32.
// buf: Xh 0, Xl 10240, Gh 20480, Ph 30720, Pl 40960   (CV_STG=51200)
// ===========================================================================
#define CV_STG 51200
#define CV_SMEM (2 * CV_STG)
__global__ __launch_bounds__(512) void conv_mma(const float* __restrict__ x,
                                                const float* __restrict__ bg,
                                                const float* __restrict__ bp) {
    extern __shared__ char sm[];
    const u32 sb = smem_u32(sm);
    const int t = threadIdx.x, lane = t & 31, wp_ = t >> 5;
    const int wm = wp_ >> 3, wn = wp_ & 7;
    const int nb = blockIdx.z, a0 = blockIdx.y * 128, l0 = blockIdx.x * 128;
    const float* X = x + (size_t)nb * CCH * HWD;

    float aG[4][2][4] = {};
    float aP[4][2][4] = {};
    float xv0[4], xv1[4];

    {
        #pragma unroll
        for (int i = 0; i < 4; ++i) {
            int e = t + i * 512; int l = e & 127; int cp = e >> 7;
            xv0[i] = X[(size_t)(2 * cp) * HWD + l0 + l];
            xv1[i] = X[(size_t)(2 * cp + 1) * HWD + l0 + l];
        }
        stage80_512(sb + 20480, d_wh + (size_t)a0 * 512, t);
        stage80_512(sb + 30720, d_wh + (size_t)(256 + a0) * 512, t);
        stage80_512(sb + 40960, d_wl + (size_t)(256 + a0) * 512, t);
        CPC;
        #pragma unroll
        for (int i = 0; i < 4; ++i) {
            int e = t + i * 512; int l = e & 127; int cp = e >> 7;
            u16 h0, q0, h1c, q1; hsplit(xv0[i], h0, q0); hsplit(xv1[i], h1c, q1);
            *(u32*)(sm + l * 80 + cp * 4) = (u32)h0 | ((u32)h1c << 16);
            *(u32*)(sm + 10240 + l * 80 + cp * 4) = (u32)q0 | ((u32)q1 << 16);
        }
    }

    #pragma unroll 1
    for (int s = 0; s < 16; ++s) {
        const int buf = s & 1;
        char* nbuf = sm + (buf ^ 1) * CV_STG;
        const u32 nbu = sb + (buf ^ 1) * CV_STG;
        if (s + 1 < 16) {
            const int k0 = (s + 1) * 32;
            #pragma unroll
            for (int i = 0; i < 4; ++i) {
                int e = t + i * 512; int l = e & 127; int cp = e >> 7;
                xv0[i] = X[(size_t)(k0 + 2 * cp) * HWD + l0 + l];
                xv1[i] = X[(size_t)(k0 + 2 * cp + 1) * HWD + l0 + l];
            }
            stage80_512(nbu + 20480, d_wh + (size_t)a0 * 512 + k0, t);
            stage80_512(nbu + 30720, d_wh + (size_t)(256 + a0) * 512 + k0, t);
            stage80_512(nbu + 40960, d_wl + (size_t)(256 + a0) * 512 + k0, t);
            CPC; CP_WAIT1;
        } else { CP_WAIT0; }
        __syncthreads();

        const u32 bu = sb + buf * CV_STG;
        #pragma unroll
        for (int ks = 0; ks < 2; ++ks) {
            const int k0 = ks * 16;
            unsigned ah[4][4], al[4][4];
            #pragma unroll
            for (int mt = 0; mt < 4; ++mt) {
                ldA80(ah[mt], bu, wm * 64 + mt * 16, k0, lane);
                ldA80(al[mt], bu + 10240, wm * 64 + mt * 16, k0, lane);
            }
            unsigned gh[4], ph[4], pl[4];
            ldA80(gh, bu + 20480, wn * 16, k0, lane);
            ldA80(ph, bu + 30720, wn * 16, k0, lane);
            ldA80(pl, bu + 40960, wn * 16, k0, lane);
            #pragma unroll
            for (int mt = 0; mt < 4; ++mt)
                #pragma unroll
                for (int n8 = 0; n8 < 2; ++n8) {
                    mma16816(aG[mt][n8], ah[mt], gh[n8], gh[2 + n8]);
                    mma16816(aP[mt][n8], ah[mt], ph[n8], ph[2 + n8]);
                    mma16816(aP[mt][n8], al[mt], ph[n8], ph[2 + n8]);
                    mma16816(aP[mt][n8], ah[mt], pl[n8], pl[2 + n8]);
                }
        }
        if (s + 1 < 16) {
            #pragma unroll
            for (int i = 0; i < 4; ++i) {
                int e = t + i * 512; int l = e & 127; int cp = e >> 7;
                u16 h0, q0, h1c, q1; hsplit(xv0[i], h0, q0); hsplit(xv1[i], h1c, q1);
                *(u32*)(nbuf + l * 80 + cp * 4) = (u32)h0 | ((u32)h1c << 16);
                *(u32*)(nbuf + 10240 + l * 80 + cp * 4) = (u32)q0 | ((u32)q1 << 16);
            }
        }
        __syncthreads();
    }

    // epilogue G (descale 1/64, +bias) -> d_gh [l][a] fp16 single
    #pragma unroll
    for (int mt = 0; mt < 4; ++mt)
        #pragma unroll
        for (int n8 = 0; n8 < 2; ++n8) {
            const int l = l0 + wm * 64 + mt * 16 + (lane >> 2);
            const int a = a0 + wn * 16 + n8 * 8 + ((lane & 3) << 1);
            const float b0 = __ldg(bg + a), b1 = __ldg(bg + a + 1);
            const size_t i0 = ((size_t)nb * HWD + l) * AA + a;
            u16 g0 = h1(aG[mt][n8][0] * 0.015625f + b0);
            u16 g1 = h1(aG[mt][n8][1] * 0.015625f + b1);
            u16 g2 = h1(aG[mt][n8][2] * 0.015625f + b0);
            u16 g3 = h1(aG[mt][n8][3] * 0.015625f + b1);
            *(u32*)(d_gh + i0) = (u32)g0 | ((u32)g1 << 16);
            *(u32*)(d_gh + i0 + (size_t)8 * AA) = (u32)g2 | ((u32)g3 << 16);
        }

    // epilogue Phi: transpose to ts[a][132] fp32, then fused 2x2 pool -> d_pp
    float* ts = (float*)sm;
    __syncthreads();
    #pragma unroll
    for (int mt = 0; mt < 4; ++mt)
        #pragma unroll
        for (int n8 = 0; n8 < 2; ++n8) {
            const int nl = wn * 16 + n8 * 8 + ((lane & 3) << 1);
            const int ml = wm * 64 + mt * 16 + (lane >> 2);
            const float b0 = __ldg(bp + a0 + nl), b1 = __ldg(bp + a0 + nl + 1);
            ts[nl * 132 + ml] = aP[mt][n8][0] * 0.015625f + b0;
            ts[(nl + 1) * 132 + ml] = aP[mt][n8][1] * 0.015625f + b1;
            ts[nl * 132 + ml + 8] = aP[mt][n8][2] * 0.015625f + b0;
            ts[(nl + 1) * 132 + ml + 8] = aP[mt][n8][3] * 0.015625f + b1;
        }
    __syncthreads();
    const int pb = l0 >> 7;
    #pragma unroll
    for (int i = 0; i < 8; ++i) {
        int e = t + i * 512; int a = e >> 5; int w = e & 31;
        float v = fmaxf(fmaxf(ts[a * 132 + 2 * w], ts[a * 132 + 2 * w + 1]),
                        fmaxf(ts[a * 132 + 64 + 2 * w], ts[a * 132 + 65 + 2 * w]));
        u16 h, l; hsplit(v, h, l);
        const size_t o = ((size_t)nb * AA + a0 + a) * PHW + pb * 32 + w;
        d_pph[o] = h; d_ppl[o] = l;
    }
}

// ===========================================================================
// cmat + fused softmax: theta . phi^T (3-term), row softmax, attn fp16 single.
// CTA 128c x 256a full row, 512 threads, K=1024 BK=64.
// buf: Ah 0(16K), Al 16384, Bh 32768(32K), Bl 65536(32K)  (CM_STG=98304)
// ===========================================================================
#define CM_STG 98304
#define CM_SMEM (2 * CM_STG)
__global__ __launch_bounds__(512) void cmat_mma() {
    extern __shared__ char sm[];
    const u32 sb = smem_u32(sm);
    const int t = threadIdx.x, lane = t & 31, wp_ = t >> 5;
    const int wm = wp_ >> 3, wn = wp_ & 7;
    const int nb = blockIdx.y, c0 = blockIdx.x * 128;
    const u16* TH = d_thh + ((size_t)nb * CCH + c0) * PHW;
    const u16* TL = d_thl + ((size_t)nb * CCH + c0) * PHW;
    const u16* PH = d_pph + (size_t)nb * AA * PHW;
    const u16* PL = d_ppl + (size_t)nb * AA * PHW;

    float acc[4][4][4] = {};

    #define STG_A(dst, src) do {                                                   \
        _Pragma("unroll")                                                          \
        for (int i_ = 0; i_ < 2; ++i_) {                                           \
            int idx_ = t + i_ * 512; int r_ = idx_ >> 3, ch_ = idx_ & 7;           \
            cpa((dst) + r_ * 128 + (((ch_ ^ (r_ & 7)) & 7) << 4),                  \
                (src) + (size_t)r_ * PHW + ch_ * 8);                               \
        } } while (0)
    #define STG_B(dst, src) do {                                                   \
        _Pragma("unroll")                                                          \
        for (int i_ = 0; i_ < 4; ++i_) {                                           \
            int idx_ = t + i_ * 512; int r_ = idx_ >> 3, ch_ = idx_ & 7;           \
            cpa((dst) + r_ * 128 + (((ch_ ^ (r_ & 7)) & 7) << 4),                  \
                (src) + (size_t)r_ * PHW + ch_ * 8);                               \
        } } while (0)

    STG_A(sb, TH); STG_A(sb + 16384, TL);
    STG_B(sb + 32768, PH); STG_B(sb + 65536, PL);
    CPC;
    #pragma unroll 1
    for (int s = 0; s < 16; ++s) {
        const int buf = s & 1;
        if (s + 1 < 16) {
            const u32 nbu = sb + (buf ^ 1) * CM_STG;
            const int k0 = (s + 1) * 64;
            STG_A(nbu, TH + k0); STG_A(nbu + 16384, TL + k0);
            STG_B(nbu + 32768, PH + k0); STG_B(nbu + 65536, PL + k0);
            CPC; CP_WAIT1;
        } else { CP_WAIT0; }
        __syncthreads();
        const u32 bu = sb + buf * CM_STG;
        #pragma unroll
        for (int ks = 0; ks < 4; ++ks) {
            const int k0 = ks * 16;
            unsigned ah[4][4], al[4][4], bh[2][4], bl[2][4];
            #pragma unroll
            for (int mt = 0; mt < 4; ++mt) {
                ldA128(ah[mt], bu, wm * 64 + mt * 16, k0, lane);
                ldA128(al[mt], bu + 16384, wm * 64 + mt * 16, k0, lane);
            }
            #pragma unroll
            for (int bt = 0; bt < 2; ++bt) {
                ldA128(bh[bt], bu + 32768, wn * 32 + bt * 16, k0, lane);
                ldA128(bl[bt], bu + 65536, wn * 32 + bt * 16, k0, lane);
            }
            #pragma unroll
            for (int mt = 0; mt < 4; ++mt)
                #pragma unroll
                for (int n8 = 0; n8 < 4; ++n8) {
                    const int bt = n8 >> 1, sl = n8 & 1;
                    mma16816(acc[mt][n8], ah[mt], bh[bt][sl], bh[bt][2 + sl]);
                    mma16816(acc[mt][n8], al[mt], bh[bt][sl], bh[bt][2 + sl]);
                    mma16816(acc[mt][n8], ah[mt], bl[bt][sl], bl[bt][2 + sl]);
                }
        }
        __syncthreads();
    }
    #undef STG_A
    #undef STG_B

    // ---- fused softmax over a=256 ----
    float* red = (float*)sm;
    const int rl = lane >> 2, l3 = lane & 3;
    float rmax[4][2], rinv[4][2];

    #pragma unroll
    for (int mt = 0; mt < 4; ++mt)
        #pragma unroll
        for (int rs = 0; rs < 2; ++rs) {
            float m = -3.0e38f;
            #pragma unroll
            for (int n8 = 0; n8 < 4; ++n8) {
                m = fmaxf(m, acc[mt][n8][rs * 2]);
                m = fmaxf(m, acc[mt][n8][rs * 2 + 1]);
            }
            m = fmaxf(m, __shfl_xor_sync(0xffffffffu, m, 1));
            m = fmaxf(m, __shfl_xor_sync(0xffffffffu, m, 2));
            if (l3 == 0) red[(((wm * 4 + mt) * 2 + rs) * 8 + rl) * 8 + wn] = m;
        }
    __syncthreads();
    #pragma unroll
    for (int mt = 0; mt < 4; ++mt)
        #pragma unroll
        for (int rs = 0; rs < 2; ++rs) {
            float m = -3.0e38f;
            #pragma unroll
            for (int w8 = 0; w8 < 8; ++w8)
                m = fmaxf(m, red[(((wm * 4 + mt) * 2 + rs) * 8 + rl) * 8 + w8]);
            rmax[mt][rs] = m;
        }
    __syncthreads();
    #pragma unroll
    for (int mt = 0; mt < 4; ++mt)
        #pragma unroll
        for (int rs = 0; rs < 2; ++rs) {
            float s = 0.f;
            #pragma unroll
            for (int n8 = 0; n8 < 4; ++n8) {
                float e0 = expf(acc[mt][n8][rs * 2] - rmax[mt][rs]);
                float e1 = expf(acc[mt][n8][rs * 2 + 1] - rmax[mt][rs]);
                acc[mt][n8][rs * 2] = e0; acc[mt][n8][rs * 2 + 1] = e1;
                s += e0 + e1;
            }
            s += __shfl_xor_sync(0xffffffffu, s, 1);
            s += __shfl_xor_sync(0xffffffffu, s, 2);
            if (l3 == 0) red[(((wm * 4 + mt) * 2 + rs) * 8 + rl) * 8 + wn] = s;
        }
    __syncthreads();
    #pragma unroll
    for (int mt = 0; mt < 4; ++mt)
        #pragma unroll
        for (int rs = 0; rs < 2; ++rs) {
            float s = 0.f;
            #pragma unroll
            for (int w8 = 0; w8 < 8; ++w8)
                s += red[(((wm * 4 + mt) * 2 + rs) * 8 + rl) * 8 + w8];
            rinv[mt][rs] = 1.0f / s;
        }

    #pragma unroll
    for (int mt = 0; mt < 4; ++mt)
        #pragma unroll
        for (int n8 = 0; n8 < 4; ++n8) {
            const int c = c0 + wm * 64 + mt * 16 + rl;
            const int a = wn * 32 + n8 * 8 + 2 * l3;
            size_t i0 = ((size_t)nb * CCH + c) * AA + a;
            u16 h0 = h1(acc[mt][n8][0] * rinv[mt][0]);
            u16 hh1 = h1(acc[mt][n8][1] * rinv[mt][0]);
            *(u32*)(d_ath + i0) = (u32)h0 | ((u32)hh1 << 16);
            i0 += (size_t)8 * AA;
            u16 h2 = h1(acc[mt][n8][2] * rinv[mt][1]);
            u16 h3 = h1(acc[mt][n8][3] * rinv[mt][1]);
            *(u32*)(d_ath + i0) = (u32)h2 | ((u32)h3 << 16);
        }
}

// ===========================================================================
// final: out[c][l] = attn_hi . G_hi + x  (1-term), K=256, BK=64
// buf: AH 0(16K), BH 16384(16K)  (FN_STG=32768)
// ===========================================================================
#define FN_STG 32768
#define FN_SMEM (2 * FN_STG)
__global__ __launch_bounds__(256) void final_mma(const float* __restrict__ x,
                                                 float* __restrict__ out) {
    extern __shared__ char sm[];
    const u32 sb = smem_u32(sm);
    const int t = threadIdx.x, lane = t & 31;
    const int wm = (t >> 5) & 1, wn = t >> 6;
    const int nb = blockIdx.z, c0 = blockIdx.y * 128, l0 = blockIdx.x * 128;
    const u16* AH = d_ath + ((size_t)nb * CCH + c0) * AA;
    const u16* BH = d_gh + ((size_t)nb * HWD + l0) * AA;

    float acc[4][4][4] = {};

    #define STG(dst, src, ld) do {                                                 \
        _Pragma("unroll")                                                          \
        for (int i_ = 0; i_ < 4; ++i_) {                                           \
            int idx_ = t + i_ * 256; int r_ = idx_ >> 3, ch_ = idx_ & 7;           \
            cpa((dst) + r_ * 128 + (((ch_ ^ (r_ & 7)) & 7) << 4),                  \
                (src) + (size_t)r_ * (ld) + ch_ * 8);                              \
        } } while (0)

    STG(sb, AH, AA); STG(sb + 16384, BH, AA);
    CPC;
    #pragma unroll 1
    for (int s = 0; s < 4; ++s) {
        const int buf = s & 1;
        if (s + 1 < 4) {
            const u32 nbu = sb + (buf ^ 1) * FN_STG;
            const int k0 = (s + 1) * 64;
            STG(nbu, AH + k0, AA); STG(nbu + 16384, BH + k0, AA);
            CPC; CP_WAIT1;
        } else { CP_WAIT0; }
        __syncthreads();
        const u32 bu = sb + buf * FN_STG;
        #pragma unroll
        for (int ks = 0; ks < 4; ++ks) {
            const int k0 = ks * 16;
            unsigned ah[4][4], bh[2][4];
            #pragma unroll
            for (int mt = 0; mt < 4; ++mt)
                ldA128(ah[mt], bu, wm * 64 + mt * 16, k0, lane);
            #pragma unroll
            for (int bt = 0; bt < 2; ++bt)
                ldA128(bh[bt], bu + 16384, wn * 32 + bt * 16, k0, lane);
            #pragma unroll
            for (int mt = 0; mt < 4; ++mt)
                #pragma unroll
                for (int n8 = 0; n8 < 4; ++n8) {
                    const int bt = n8 >> 1, sl = n8 & 1;
                    mma16816(acc[mt][n8], ah[mt], bh[bt][sl], bh[bt][2 + sl]);
                }
        }
        __syncthreads();
    }
    #undef STG

    #pragma unroll
    for (int mt = 0; mt < 4; ++mt)
        #pragma unroll
        for (int n8 = 0; n8 < 4; ++n8) {
            const int c = c0 + wm * 64 + mt * 16 + (lane >> 2);
            const int l = l0 + wn * 32 + n8 * 8 + ((lane & 3) << 1);
            size_t i0 = ((size_t)nb * CCH + c) * HWD + l;
            float2 xv = *(const float2*)(x + i0);
            float2 o0; o0.x = acc[mt][n8][0] + xv.x; o0.y = acc[mt][n8][1] + xv.y;
            *(float2*)(out + i0) = o0;
            i0 += (size_t)8 * HWD;
            float2 xw = *(const float2*)(x + i0);
            float2 o1; o1.x = acc[mt][n8][2] + xw.x; o1.y = acc[mt][n8][3] + xw.y;
            *(float2*)(out + i0) = o1;
        }
}

// ===========================================================================
extern "C" void kernel_launch(void* const* d_in, const int* in_sizes, int n_in,
                              void* d_out, int out_size) {
    (void)in_sizes; (void)n_in; (void)out_size;
    const float* x  = (const float*)d_in[0];
    const float* wg = (const float*)d_in[1];
    const float* bg = (const float*)d_in[2];
    const float* wp = (const float*)d_in[3];
    const float* bp = (const float*)d_in[4];
    float* out = (float*)d_out;

    cudaFuncSetAttribute(conv_mma,  cudaFuncAttributeMaxDynamicSharedMemorySize, CV_SMEM);
    cudaFuncSetAttribute(cmat_mma,  cudaFuncAttributeMaxDynamicSharedMemorySize, CM_SMEM);
    cudaFuncSetAttribute(final_mma, cudaFuncAttributeMaxDynamicSharedMemorySize, FN_SMEM);

    split_w_k<<<1024, 256>>>(wg, wp);
    pool_theta_k<<<65536, 256>>>(x);

    conv_mma<<<dim3(32, 2, NB), 512, CV_SMEM>>>(x, bg, bp);

    cmat_mma<<<dim3(4, NB), 512, CM_SMEM>>>();

    final_mma<<<dim3(32, 4, NB), 256, FN_SMEM>>>(x, out);
}